// round 12
// baseline (speedup 1.0000x reference)
#include <cuda_runtime.h>
#include <cstdint>
#include <cstddef>

#define BSZ  16384
#define SDIM 1024
#define ADIM 64
#define HID  1024
#define REC  1024
#define LATD 1024

// Scratch
__device__ float g_x [(size_t)BSZ * HID];
__device__ float g_gi[(size_t)BSZ * 3 * REC];
__device__ float g_gh[(size_t)BSZ * 3 * REC];

// ---- ambiguous-group fix machinery ----
#define FIX_TAU  2e-4f
#define AMB_CAP  16384
#define FIX_ROWS 512
__device__ int   g_namb;
__device__ int   g_nrows;
__device__ int   g_amb[AMB_CAP];
__device__ int   g_rowlist[FIX_ROWS];
__device__ int   g_rowflag[BSZ];
__device__ float g_fin [(size_t)FIX_ROWS * 1088];
__device__ float g_fdet[(size_t)FIX_ROWS * 1024];
__device__ float g_fobs[(size_t)FIX_ROWS * 1024];
__device__ float g_fx  [(size_t)FIX_ROWS * 1024];
__device__ float g_fgi [(size_t)FIX_ROWS * 3072];
__device__ float g_fgh [(size_t)FIX_ROWS * 3072];
__device__ float g_fh  [(size_t)FIX_ROWS * 1024];
__device__ float g_flog[(size_t)FIX_ROWS * 1024];

__device__ __forceinline__ uint32_t smem_u32(const void* p) {
    uint32_t a;
    asm("{ .reg .u64 t; cvta.to.shared.u64 t, %1; cvt.u32.u64 %0, t; }"
        : "=r"(a) : "l"(p));
    return a;
}

// ---------------- bf16x2-split mma.sync GEMM, swizzled smem + ldmatrix ----------------
// CTA 128x128, 512 thr (16 warps 4x4), warp tile 32x32, K-chunk 32.
// Component = 128 rows x 16 words; word(r,kw) = r*16 + (kw ^ (((r>>1)&3)<<2)).
// Fragments via ldmatrix.m8n8.x4 (A: rows x k-halves; B: n-pair x k-halves).
#define MMA_THR 512
#define COMP_W  (128 * 16)
#define STG_W   (4 * COMP_W)
#define STG_BYTES (STG_W * 4)                 // 32768
#define SMEM_CA  (2 * STG_BYTES)              // 65536
#define OFF_AH 0
#define OFF_AL COMP_W
#define OFF_BH (2 * COMP_W)
#define OFF_BL (3 * COMP_W)

__device__ __forceinline__ void mma16(float c[4], const uint32_t a[4], const uint32_t b[2]) {
    asm volatile("mma.sync.aligned.m16n8k16.row.col.f32.bf16.bf16.f32 "
                 "{%0,%1,%2,%3}, {%4,%5,%6,%7}, {%8,%9}, {%0,%1,%2,%3};"
                 : "+f"(c[0]), "+f"(c[1]), "+f"(c[2]), "+f"(c[3])
                 : "r"(a[0]), "r"(a[1]), "r"(a[2]), "r"(a[3]), "r"(b[0]), "r"(b[1]));
}
#define LDSM4(r0, r1, r2, r3, addr) \
    asm volatile("ldmatrix.sync.aligned.m8n8.x4.shared.b16 {%0,%1,%2,%3}, [%4];" \
                 : "=r"(r0), "=r"(r1), "=r"(r2), "=r"(r3) : "r"(addr))

__device__ __forceinline__ void splitbf(float x0, float x1, uint32_t& hi, uint32_t& lo) {
    uint32_t u0 = __float_as_uint(x0), u1 = __float_as_uint(x1);
    uint32_t h;
    asm("prmt.b32 %0, %1, %2, 0x7632;" : "=r"(h) : "r"(u0), "r"(u1));
    hi = h;
    float f0 = __uint_as_float(u0 & 0xFFFF0000u);
    float f1 = __uint_as_float(u1 & 0xFFFF0000u);
    float r0 = x0 - f0;
    float r1 = x1 - f1;
    asm("cvt.rn.bf16x2.f32 %0, %1, %2;" : "=r"(lo) : "f"(r1), "f"(r0));
}
__device__ __forceinline__ void sts128(uint32_t addr, uint32_t a, uint32_t b,
                                       uint32_t c, uint32_t d) {
    asm volatile("st.shared.v4.b32 [%0], {%1,%2,%3,%4};"
                 :: "r"(addr), "r"(a), "r"(b), "r"(c), "r"(d) : "memory");
}

__global__ __launch_bounds__(MMA_THR, 1)
void mma_gemm(const float* __restrict__ A1, int K1,
              const float* __restrict__ A2, int K2,
              const unsigned char* __restrict__ mask,
              const float* __restrict__ B,
              const float* __restrict__ bias,
              float* __restrict__ C, int Ntot)
{
    extern __shared__ __align__(16) float sm[];
    const uint32_t sbase = smem_u32(sm);

    const int K  = K1 + K2;
    const int KC = K >> 5;
    const int bm = blockIdx.y << 7;
    const int bn = blockIdx.x << 7;
    const int t  = threadIdx.x;
    const int wid  = t >> 5;
    const int lane = t & 31;
    const int g = lane >> 2;
    const int c = lane & 3;
    const int wm = (wid >> 2) << 5;
    const int wn = (wid & 3) << 5;

    // copy mapping
    const int rowA = t >> 2;
    const int kq0  = (t & 3) << 3;
    const int kw0s = ((t & 3) << 2) ^ (((rowA >> 1) & 3) << 2);
    const bool masked = (mask != nullptr) && mask[bm + rowA];

    float4 ar0, ar1, br0, br1;

    auto ldg = [&](int kc) {
        const int kg = (kc << 5) + kq0;
        if (kg < K1) {
            if (masked) {
                ar0 = make_float4(0.f, 0.f, 0.f, 0.f);
                ar1 = ar0;
            } else {
                const float* p = A1 + (size_t)(bm + rowA) * K1 + kg;
                ar0 = *reinterpret_cast<const float4*>(p);
                ar1 = *reinterpret_cast<const float4*>(p + 4);
            }
        } else {
            const float* p = A2 + (size_t)(bm + rowA) * K2 + (kg - K1);
            ar0 = *reinterpret_cast<const float4*>(p);
            ar1 = *reinterpret_cast<const float4*>(p + 4);
        }
        const float* q = B + (size_t)(bn + rowA) * K + kg;
        br0 = *reinterpret_cast<const float4*>(q);
        br1 = *reinterpret_cast<const float4*>(q + 4);
    };

    auto sts = [&](int buf) {
        const uint32_t base = sbase + (uint32_t)buf * STG_BYTES;
        const uint32_t off = (uint32_t)(rowA * 16 + kw0s) * 4u;
        uint32_t h0, h1, h2, h3, l0, l1, l2, l3;
        splitbf(ar0.x, ar0.y, h0, l0); splitbf(ar0.z, ar0.w, h1, l1);
        splitbf(ar1.x, ar1.y, h2, l2); splitbf(ar1.z, ar1.w, h3, l3);
        sts128(base + OFF_AH * 4u + off, h0, h1, h2, h3);
        sts128(base + OFF_AL * 4u + off, l0, l1, l2, l3);
        splitbf(br0.x, br0.y, h0, l0); splitbf(br0.z, br0.w, h1, l1);
        splitbf(br1.x, br1.y, h2, l2); splitbf(br1.z, br1.w, h3, l3);
        sts128(base + OFF_BH * 4u + off, h0, h1, h2, h3);
        sts128(base + OFF_BL * 4u + off, l0, l1, l2, l3);
    };

    // ldmatrix per-lane byte offsets (within a component), for i/jp and ks
    const int lsel  = lane & 15;
    const int whalf = (lane >> 4) & 1;
    uint32_t offA[2][2], offB[2][2];
#pragma unroll
    for (int i = 0; i < 2; i++) {
        int r = wm + (i << 4) + lsel;
        int s = ((r >> 1) & 3) << 2;
#pragma unroll
        for (int ks = 0; ks < 2; ks++) {
            int w = ((ks << 3) + (whalf << 2)) ^ s;
            offA[i][ks] = (uint32_t)(r * 16 + w) * 4u;
        }
    }
#pragma unroll
    for (int jp = 0; jp < 2; jp++) {
        int r = wn + (jp << 4) + lsel;
        int s = ((r >> 1) & 3) << 2;
#pragma unroll
        for (int ks = 0; ks < 2; ks++) {
            int w = ((ks << 3) + (whalf << 2)) ^ s;
            offB[jp][ks] = (uint32_t)(r * 16 + w) * 4u;
        }
    }

    float acc[2][4][4];
#pragma unroll
    for (int i = 0; i < 2; i++)
#pragma unroll
        for (int j = 0; j < 4; j++)
#pragma unroll
            for (int r = 0; r < 4; r++) acc[i][j][r] = 0.f;

    ldg(0); sts(0);
    __syncthreads();
    ldg(1);

    for (int k = 0; k < KC; k++) {
        if (k + 1 < KC) sts((k + 1) & 1);

        const uint32_t base = sbase + (uint32_t)(k & 1) * STG_BYTES;

#pragma unroll
        for (int ks = 0; ks < 2; ks++) {
            uint32_t aH[2][4], aL[2][4], bH[4][2], bL[4][2];
#pragma unroll
            for (int i = 0; i < 2; i++) {
                LDSM4(aH[i][0], aH[i][1], aH[i][2], aH[i][3],
                      base + OFF_AH * 4u + offA[i][ks]);
                LDSM4(aL[i][0], aL[i][1], aL[i][2], aL[i][3],
                      base + OFF_AL * 4u + offA[i][ks]);
            }
#pragma unroll
            for (int jp = 0; jp < 2; jp++) {
                LDSM4(bH[jp * 2][0], bH[jp * 2 + 1][0], bH[jp * 2][1], bH[jp * 2 + 1][1],
                      base + OFF_BH * 4u + offB[jp][ks]);
                LDSM4(bL[jp * 2][0], bL[jp * 2 + 1][0], bL[jp * 2][1], bL[jp * 2 + 1][1],
                      base + OFF_BL * 4u + offB[jp][ks]);
            }
#pragma unroll
            for (int i = 0; i < 2; i++)
#pragma unroll
                for (int j = 0; j < 4; j++) mma16(acc[i][j], aH[i], bH[j]);
#pragma unroll
            for (int i = 0; i < 2; i++)
#pragma unroll
                for (int j = 0; j < 4; j++) mma16(acc[i][j], aL[i], bH[j]);
#pragma unroll
            for (int i = 0; i < 2; i++)
#pragma unroll
                for (int j = 0; j < 4; j++) mma16(acc[i][j], aH[i], bL[j]);
        }
        if (k + 2 < KC) ldg(k + 2);
        __syncthreads();
    }

#pragma unroll
    for (int i = 0; i < 2; i++) {
        int row0 = bm + wm + (i << 4) + g;
        int row1 = row0 + 8;
#pragma unroll
        for (int j = 0; j < 4; j++) {
            int col = bn + wn + (j << 3) + (c << 1);
            float2 b2 = *reinterpret_cast<const float2*>(bias + col);
            float2 v0 = make_float2(acc[i][j][0] + b2.x, acc[i][j][1] + b2.y);
            float2 v1 = make_float2(acc[i][j][2] + b2.x, acc[i][j][3] + b2.y);
            *reinterpret_cast<float2*>(C + (size_t)row0 * Ntot + col) = v0;
            *reinterpret_cast<float2*>(C + (size_t)row1 * Ntot + col) = v1;
        }
    }
}

// ---------------- fp32 FFMA GEMM (fix path) ----------------
#define GBM 128
#define GBN 128
#define GBK 16
#define GTM 8
#define GTN 8

__global__ __launch_bounds__(256, 2)
void gemm_f32(const float* __restrict__ A1, int K1,
              const float* __restrict__ A2, int K2,
              const float* __restrict__ B,
              const float* __restrict__ bias,
              float* __restrict__ C, int N)
{
    __shared__ __align__(16) float As[GBK][GBM];
    __shared__ __align__(16) float Bs[GBK][GBN];
    const int K  = K1 + K2;
    const int bm = blockIdx.y * GBM;
    const int bn = blockIdx.x * GBN;
    const int t  = threadIdx.x;
    const int tx = t & 15;
    const int ty = t >> 4;

    float acc[GTM][GTN];
#pragma unroll
    for (int i = 0; i < GTM; i++)
#pragma unroll
        for (int j = 0; j < GTN; j++) acc[i][j] = 0.f;

    for (int kt = 0; kt < K; kt += GBK) {
#pragma unroll
        for (int q = 0; q < 2; q++) {
            int li  = t * 2 + q;
            int row = li >> 2;
            int kq  = (li & 3) << 2;
            int kg  = kt + kq;
            {
                int m = bm + row;
                float4 v;
                if (kg < K1) v = *reinterpret_cast<const float4*>(A1 + (size_t)m * K1 + kg);
                else         v = *reinterpret_cast<const float4*>(A2 + (size_t)m * K2 + (kg - K1));
                As[kq + 0][row] = v.x; As[kq + 1][row] = v.y;
                As[kq + 2][row] = v.z; As[kq + 3][row] = v.w;
            }
            {
                int n = bn + row;
                float4 w = *reinterpret_cast<const float4*>(B + (size_t)n * K + kg);
                Bs[kq + 0][row] = w.x; Bs[kq + 1][row] = w.y;
                Bs[kq + 2][row] = w.z; Bs[kq + 3][row] = w.w;
            }
        }
        __syncthreads();
#pragma unroll
        for (int k = 0; k < GBK; k++) {
            float4 a0 = *reinterpret_cast<const float4*>(&As[k][ty * GTM]);
            float4 a1 = *reinterpret_cast<const float4*>(&As[k][ty * GTM + 4]);
            float4 b0 = *reinterpret_cast<const float4*>(&Bs[k][tx * GTN]);
            float4 b1 = *reinterpret_cast<const float4*>(&Bs[k][tx * GTN + 4]);
            float a[8] = {a0.x, a0.y, a0.z, a0.w, a1.x, a1.y, a1.z, a1.w};
            float b[8] = {b0.x, b0.y, b0.z, b0.w, b1.x, b1.y, b1.z, b1.w};
#pragma unroll
            for (int i = 0; i < GTM; i++)
#pragma unroll
                for (int j = 0; j < GTN; j++)
                    acc[i][j] = fmaf(a[i], b[j], acc[i][j]);
        }
        __syncthreads();
    }
#pragma unroll
    for (int i = 0; i < GTM; i++) {
        int m = bm + ty * GTM + i;
        float* crow = C + (size_t)m * N + bn + tx * GTN;
#pragma unroll
        for (int j = 0; j < GTN; j++)
            crow[j] = acc[i][j] + bias[bn + tx * GTN + j];
    }
}

// ---------------- GRU elementwise combine ----------------
__global__ void gru_kernel(const float* __restrict__ deter,
                           const unsigned char* __restrict__ first,
                           float* __restrict__ h_out)
{
    int i = blockIdx.x * blockDim.x + threadIdx.x;
    if (i >= BSZ * REC) return;
    int m = i >> 10;
    int n = i & 1023;
    size_t base = (size_t)m * (3 * REC) + n;
    float ir  = g_gi[base];
    float iz  = g_gi[base + REC];
    float i_n = g_gi[base + 2 * REC];
    float hr  = g_gh[base];
    float hz  = g_gh[base + REC];
    float h_n = g_gh[base + 2 * REC];
    float d = first[m] ? 0.f : deter[i];
    float r  = 1.f / (1.f + expf(-(ir + hr)));
    float z  = 1.f / (1.f + expf(-(iz + hz)));
    float nn = tanhf(i_n + r * h_n);
    h_out[i] = (1.f - z) * nn + z * d;
}

// ---------------- threefry2x32 + gumbel ----------------
__device__ __forceinline__ uint32_t threefry_bits(uint32_t x1in)
{
    const uint32_t ks0 = 0u;
    const uint32_t ks1 = 42u;
    const uint32_t ks2 = 0x1BD11BDAu ^ ks0 ^ ks1;
    uint32_t x0 = 0u + ks0;
    uint32_t x1 = x1in + ks1;
#define TF_R(r) { x0 += x1; x1 = __funnelshift_l(x1, x1, (r)); x1 ^= x0; }
    TF_R(13) TF_R(15) TF_R(26) TF_R(6)
    x0 += ks1; x1 += ks2 + 1u;
    TF_R(17) TF_R(29) TF_R(16) TF_R(24)
    x0 += ks2; x1 += ks0 + 2u;
    TF_R(13) TF_R(15) TF_R(26) TF_R(6)
    x0 += ks0; x1 += ks1 + 3u;
    TF_R(17) TF_R(29) TF_R(16) TF_R(24)
    x0 += ks1; x1 += ks2 + 4u;
    TF_R(13) TF_R(15) TF_R(26) TF_R(6)
    x0 += ks2; x1 += ks0 + 5u;
#undef TF_R
    return x0 ^ x1;
}

__device__ __forceinline__ float gumbel_at(uint32_t idx)
{
    uint32_t bits = threefry_bits(idx);
    float f = __uint_as_float((bits >> 9) | 0x3f800000u) - 1.0f;
    float u = fmaxf(f, 1.17549435e-38f);
    float inner = -logf(u);
    return -__logf(inner);
}

__global__ void sample_kernel(const float* __restrict__ logits,
                              float* __restrict__ stoch_out)
{
    int g = blockIdx.x * blockDim.x + threadIdx.x;
    if (g >= BSZ * 32) return;
    const float4* lrow = reinterpret_cast<const float4*>(logits + (size_t)g * 32);
    float best = -3.4e38f, second = -3.4e38f;
    int   bi   = 0;
    uint32_t base = (uint32_t)g * 32u;
#pragma unroll
    for (int q = 0; q < 8; q++) {
        float4 lv = lrow[q];
        float l4[4] = {lv.x, lv.y, lv.z, lv.w};
#pragma unroll
        for (int ci = 0; ci < 4; ci++) {
            int d = q * 4 + ci;
            float s = l4[ci] + gumbel_at(base + (uint32_t)d);
            if (s > best) { second = best; best = s; bi = d; }
            else if (s > second) second = s;
        }
    }
    float4* dst = reinterpret_cast<float4*>(stoch_out + (size_t)g * 32);
#pragma unroll
    for (int q = 0; q < 8; q++) {
        float4 v;
        v.x = (bi == q * 4 + 0) ? 1.f : 0.f;
        v.y = (bi == q * 4 + 1) ? 1.f : 0.f;
        v.z = (bi == q * 4 + 2) ? 1.f : 0.f;
        v.w = (bi == q * 4 + 3) ? 1.f : 0.f;
        dst[q] = v;
    }
    if (best - second < FIX_TAU) {
        int slot = atomicAdd(&g_namb, 1);
        if (slot < AMB_CAP) g_amb[slot] = g;
    }
}

// ---------------- fix path ----------------
__global__ void init_fix()
{
    int t = blockIdx.x * blockDim.x + threadIdx.x;
    if (t == 0) { g_namb = 0; g_nrows = 0; }
    for (int i = t; i < BSZ; i += gridDim.x * blockDim.x) g_rowflag[i] = 0;
}

__global__ void gather_rows(const float* __restrict__ stoch,
                            const float* __restrict__ deter,
                            const float* __restrict__ action,
                            const float* __restrict__ obs,
                            const unsigned char* __restrict__ first)
{
    __shared__ int s_row, s_slot;
    int namb = min(g_namb, AMB_CAP);
    for (int e = blockIdx.x; e < namb; e += gridDim.x) {
        if (threadIdx.x == 0) {
            int row = g_amb[e] >> 5;
            int slot = -1;
            if (atomicExch(&g_rowflag[row], 1) == 0) {
                int s = atomicAdd(&g_nrows, 1);
                if (s < FIX_ROWS) { g_rowlist[s] = row; slot = s; }
            }
            s_row = row; s_slot = slot;
        }
        __syncthreads();
        int slot = s_slot, row = s_row;
        if (slot >= 0) {
            bool f = first[row] != 0;
            for (int j = threadIdx.x; j < SDIM; j += blockDim.x)
                g_fin[(size_t)slot * 1088 + j] = f ? 0.f : stoch[(size_t)row * SDIM + j];
            for (int j = threadIdx.x; j < ADIM; j += blockDim.x)
                g_fin[(size_t)slot * 1088 + SDIM + j] = action[(size_t)row * ADIM + j];
            for (int j = threadIdx.x; j < REC; j += blockDim.x)
                g_fdet[(size_t)slot * 1024 + j] = f ? 0.f : deter[(size_t)row * REC + j];
            for (int j = threadIdx.x; j < HID; j += blockDim.x)
                g_fobs[(size_t)slot * 1024 + j] = obs[(size_t)row * HID + j];
        }
        __syncthreads();
    }
}

__global__ void fgru_kernel()
{
    int i = blockIdx.x * blockDim.x + threadIdx.x;
    if (i >= FIX_ROWS * 1024) return;
    int r = i >> 10, n = i & 1023;
    size_t base = (size_t)r * 3072 + n;
    float ir  = g_fgi[base];
    float iz  = g_fgi[base + 1024];
    float i_n = g_fgi[base + 2048];
    float hr  = g_fgh[base];
    float hz  = g_fgh[base + 1024];
    float h_n = g_fgh[base + 2048];
    float d = g_fdet[i];
    float rr = 1.f / (1.f + expf(-(ir + hr)));
    float zz = 1.f / (1.f + expf(-(iz + hz)));
    float nn = tanhf(i_n + rr * h_n);
    g_fh[i] = (1.f - zz) * nn + zz * d;
}

__global__ void fix_sample(float* __restrict__ stoch_out)
{
    int idx = blockIdx.x * blockDim.x + threadIdx.x;
    int r = idx >> 5, gl = idx & 31;
    if (r >= min(g_nrows, FIX_ROWS)) return;
    int row = g_rowlist[r];
    const float* l = g_flog + (size_t)r * 1024 + gl * 32;
    uint32_t base = ((uint32_t)row * 32u + (uint32_t)gl) * 32u;
    float best = -3.4e38f;
    int bi = 0;
#pragma unroll
    for (int d = 0; d < 32; d++) {
        float s = l[d] + gumbel_at(base + (uint32_t)d);
        if (s > best) { best = s; bi = d; }
    }
    float* dst = stoch_out + (size_t)row * 1024 + gl * 32;
#pragma unroll
    for (int d = 0; d < 32; d++) dst[d] = (d == bi) ? 1.f : 0.f;
}

// ---------------- launch ----------------
extern "C" void kernel_launch(void* const* d_in, const int* in_sizes, int n_in,
                              void* d_out, int out_size)
{
    (void)in_sizes; (void)n_in; (void)out_size;
    const float* stoch  = (const float*)d_in[0];
    const float* deter  = (const float*)d_in[1];
    const float* action = (const float*)d_in[3];
    const float* obs    = (const float*)d_in[4];
    const unsigned char* first = (const unsigned char*)d_in[5];
    const float* W_in   = (const float*)d_in[6];
    const float* b_in   = (const float*)d_in[7];
    const float* W_ih   = (const float*)d_in[8];
    const float* b_ih   = (const float*)d_in[9];
    const float* W_hh   = (const float*)d_in[10];
    const float* b_hh   = (const float*)d_in[11];
    const float* W_post = (const float*)d_in[14];
    const float* b_post = (const float*)d_in[15];

    float* out        = (float*)d_out;
    float* h_out      = out;
    float* stoch_out  = out + (size_t)BSZ * LATD;
    float* logits_out = out + 2 * (size_t)BSZ * LATD;

    float *xp, *gip, *ghp;
    float *fin, *fdet, *fobs, *fx, *fgi, *fgh, *fh, *flog;
    cudaGetSymbolAddress((void**)&xp,  g_x);
    cudaGetSymbolAddress((void**)&gip, g_gi);
    cudaGetSymbolAddress((void**)&ghp, g_gh);
    cudaGetSymbolAddress((void**)&fin,  g_fin);
    cudaGetSymbolAddress((void**)&fdet, g_fdet);
    cudaGetSymbolAddress((void**)&fobs, g_fobs);
    cudaGetSymbolAddress((void**)&fx,   g_fx);
    cudaGetSymbolAddress((void**)&fgi,  g_fgi);
    cudaGetSymbolAddress((void**)&fgh,  g_fgh);
    cudaGetSymbolAddress((void**)&fh,   g_fh);
    cudaGetSymbolAddress((void**)&flog, g_flog);

    cudaFuncSetAttribute(mma_gemm, cudaFuncAttributeMaxDynamicSharedMemorySize, SMEM_CA);

    dim3 thr(MMA_THR);

    init_fix<<<64, 256>>>();

    // ---- main bf16x2-split path ----
    mma_gemm<<<dim3(HID / 128, BSZ / 128), thr, SMEM_CA>>>(
        stoch, SDIM, action, ADIM, first, W_in, b_in, xp, HID);
    mma_gemm<<<dim3(3 * REC / 128, BSZ / 128), thr, SMEM_CA>>>(
        xp, HID, xp, 0, nullptr, W_ih, b_ih, gip, 3 * REC);
    mma_gemm<<<dim3(3 * REC / 128, BSZ / 128), thr, SMEM_CA>>>(
        deter, REC, deter, 0, first, W_hh, b_hh, ghp, 3 * REC);
    gru_kernel<<<(BSZ * REC) / 256, 256>>>(deter, first, h_out);
    mma_gemm<<<dim3(LATD / 128, BSZ / 128), thr, SMEM_CA>>>(
        h_out, REC, obs, HID, nullptr, W_post, b_post, logits_out, LATD);
    sample_kernel<<<(BSZ * 32) / 256, 256>>>(logits_out, stoch_out);

    // ---- fp32 fix path for near-tie groups ----
    gather_rows<<<256, 256>>>(stoch, deter, action, obs, first);
    gemm_f32<<<dim3(HID / GBN, FIX_ROWS / GBM), dim3(256)>>>(
        fin, 1088, fin, 0, W_in, b_in, fx, HID);
    gemm_f32<<<dim3(3 * REC / GBN, FIX_ROWS / GBM), dim3(256)>>>(
        fx, 1024, fx, 0, W_ih, b_ih, fgi, 3 * REC);
    gemm_f32<<<dim3(3 * REC / GBN, FIX_ROWS / GBM), dim3(256)>>>(
        fdet, 1024, fdet, 0, W_hh, b_hh, fgh, 3 * REC);
    fgru_kernel<<<(FIX_ROWS * 1024) / 256, 256>>>();
    gemm_f32<<<dim3(LATD / GBN, FIX_ROWS / GBM), dim3(256)>>>(
        fh, 1024, fobs, 1024, W_post, b_post, flog, LATD);
    fix_sample<<<(FIX_ROWS * 32) / 256, 256>>>(stoch_out);
}

// round 13
// speedup vs baseline: 1.0838x; 1.0838x over previous
#include <cuda_runtime.h>
#include <cstdint>
#include <cstddef>

#define BSZ  16384
#define SDIM 1024
#define ADIM 64
#define HID  1024
#define REC  1024
#define LATD 1024

// Scratch
__device__ float g_gi[(size_t)BSZ * 3 * REC];
__device__ float g_gh[(size_t)BSZ * 3 * REC];
// fused-weight scratch
__device__ float g_wt[(size_t)1280 * 1024];   // W_in^T, rows >=1088 zero
__device__ float g_wc[(size_t)3072 * 1280];   // W_comb = W_ih @ W_in (cols>=1088 zero)
__device__ float g_bc[3072];                  // b_comb
__device__ float g_zb[1280];                  // zero bias (bss => 0)

// ---- ambiguous-group fix machinery ----
#define FIX_TAU  2e-4f
#define AMB_CAP  16384
#define FIX_ROWS 512
__device__ int   g_namb;
__device__ int   g_nrows;
__device__ int   g_amb[AMB_CAP];
__device__ int   g_rowlist[FIX_ROWS];
__device__ int   g_rowflag[BSZ];
__device__ float g_fin [(size_t)FIX_ROWS * 1088];
__device__ float g_fdet[(size_t)FIX_ROWS * 1024];
__device__ float g_fobs[(size_t)FIX_ROWS * 1024];
__device__ float g_fx  [(size_t)FIX_ROWS * 1024];
__device__ float g_fgi [(size_t)FIX_ROWS * 3072];
__device__ float g_fgh [(size_t)FIX_ROWS * 3072];
__device__ float g_fh  [(size_t)FIX_ROWS * 1024];
__device__ float g_flog[(size_t)FIX_ROWS * 1024];

__device__ __forceinline__ uint32_t smem_u32(const void* p) {
    uint32_t a;
    asm("{ .reg .u64 t; cvta.to.shared.u64 t, %1; cvt.u32.u64 %0, t; }"
        : "=r"(a) : "l"(p));
    return a;
}

// ---------------- prep kernels for fused W_comb ----------------
__global__ void transpose_win(const float* __restrict__ W_in)
{
    __shared__ float tile[32][33];
    int j0 = blockIdx.x << 5, h0 = blockIdx.y << 5;
    int tx = threadIdx.x, ty = threadIdx.y;   // 32 x 8
#pragma unroll
    for (int i = 0; i < 4; i++) {
        int h = h0 + ty + i * 8, j = j0 + tx;
        tile[ty + i * 8][tx] = (j < SDIM + ADIM) ? W_in[(size_t)h * (SDIM + ADIM) + j] : 0.f;
    }
    __syncthreads();
#pragma unroll
    for (int i = 0; i < 4; i++) {
        int j = j0 + ty + i * 8, h = h0 + tx;
        g_wt[(size_t)j * 1024 + h] = tile[tx][ty + i * 8];
    }
}

__global__ void bcomb_kernel(const float* __restrict__ W_ih,
                             const float* __restrict__ b_in,
                             const float* __restrict__ b_ih)
{
    int n = blockIdx.x * (blockDim.x >> 5) + (threadIdx.x >> 5);
    if (n >= 3072) return;
    int lane = threadIdx.x & 31;
    float s = 0.f;
    const float* row = W_ih + (size_t)n * 1024;
    for (int h = lane; h < 1024; h += 32) s += row[h] * b_in[h];
#pragma unroll
    for (int o = 16; o; o >>= 1) s += __shfl_xor_sync(0xFFFFFFFFu, s, o);
    if (lane == 0) g_bc[n] = s + b_ih[n];
}

// ---------------- bf16x2-split mma.sync GEMM, 128x256 tile ----------------
// CTA 128x256, 512 thr (16 warps 4x4), warp tile 32x64, K-chunk 32.
// Component layouts: A 128x16 words, B 256x16 words;
//   word(r,kw) = r*16 + (kw ^ (((r>>1)&3)<<2))  (conflict-free STS.128 + LDS.32)
#define MMA_THR 512
#define COMPA_W (128 * 16)                    // 2048
#define COMPB_W (256 * 16)                    // 4096
#define STG_W   (2 * COMPA_W + 2 * COMPB_W)   // 12288 words
#define STG_BYTES (STG_W * 4)                 // 49152
#define SMEM_CA  (2 * STG_BYTES)              // 98304
#define OFF_AH 0
#define OFF_AL COMPA_W
#define OFF_BH (2 * COMPA_W)
#define OFF_BL (2 * COMPA_W + COMPB_W)

__device__ __forceinline__ void mma16(float c[4], const uint32_t a[4], const uint32_t b[2]) {
    asm volatile("mma.sync.aligned.m16n8k16.row.col.f32.bf16.bf16.f32 "
                 "{%0,%1,%2,%3}, {%4,%5,%6,%7}, {%8,%9}, {%0,%1,%2,%3};"
                 : "+f"(c[0]), "+f"(c[1]), "+f"(c[2]), "+f"(c[3])
                 : "r"(a[0]), "r"(a[1]), "r"(a[2]), "r"(a[3]), "r"(b[0]), "r"(b[1]));
}
__device__ __forceinline__ void splitbf(float x0, float x1, uint32_t& hi, uint32_t& lo) {
    uint32_t u0 = __float_as_uint(x0), u1 = __float_as_uint(x1);
    uint32_t h;
    asm("prmt.b32 %0, %1, %2, 0x7632;" : "=r"(h) : "r"(u0), "r"(u1));
    hi = h;
    float f0 = __uint_as_float(u0 & 0xFFFF0000u);
    float f1 = __uint_as_float(u1 & 0xFFFF0000u);
    float r0 = x0 - f0;
    float r1 = x1 - f1;
    asm("cvt.rn.bf16x2.f32 %0, %1, %2;" : "=r"(lo) : "f"(r1), "f"(r0));
}
__device__ __forceinline__ void sts128(uint32_t addr, uint32_t a, uint32_t b,
                                       uint32_t c, uint32_t d) {
    asm volatile("st.shared.v4.b32 [%0], {%1,%2,%3,%4};"
                 :: "r"(addr), "r"(a), "r"(b), "r"(c), "r"(d) : "memory");
}

__global__ __launch_bounds__(MMA_THR, 1)
void mma_gemm(const float* __restrict__ A1, int K1,
              const float* __restrict__ A2, int K2,
              const unsigned char* __restrict__ mask,
              const float* __restrict__ B, int Bstr,
              const float* __restrict__ bias,
              float* __restrict__ C, int Ntot)
{
    extern __shared__ __align__(16) float sm[];
    const uint32_t sbase = smem_u32(sm);

    const int K  = K1 + K2;
    const int KC = K >> 5;
    const int bm = blockIdx.y << 7;
    const int bn = blockIdx.x << 8;
    const int t  = threadIdx.x;
    const int wid  = t >> 5;
    const int lane = t & 31;
    const int g = lane >> 2;
    const int c = lane & 3;
    const int wm = (wid >> 2) << 5;   // 0,32,64,96
    const int wn = (wid & 3) << 6;    // 0,64,128,192

    // copy mapping: A row = t>>2, 8 floats at kq0; B row = t>>1, 16 floats at kqB
    const int rowA = t >> 2;
    const int kq0  = (t & 3) << 3;
    const int kw0s = ((t & 3) << 2) ^ (((rowA >> 1) & 3) << 2);
    const int rowB = t >> 1;
    const int kqB  = (t & 1) << 4;
    const int wb0  = (t & 1) << 3;
    const int sB   = ((rowB >> 1) & 3) << 2;
    const uint32_t offB0 = (uint32_t)(rowB * 16 + ((wb0 + 0) ^ sB)) * 4u;
    const uint32_t offB1 = (uint32_t)(rowB * 16 + ((wb0 + 4) ^ sB)) * 4u;
    const bool masked = (mask != nullptr) && mask[bm + rowA];

    float4 ar0, ar1, br[4];

    auto ldg = [&](int kc) {
        const int kg = (kc << 5) + kq0;
        if (kg < K1) {
            if (masked) {
                ar0 = make_float4(0.f, 0.f, 0.f, 0.f);
                ar1 = ar0;
            } else {
                const float* p = A1 + (size_t)(bm + rowA) * K1 + kg;
                ar0 = *reinterpret_cast<const float4*>(p);
                ar1 = *reinterpret_cast<const float4*>(p + 4);
            }
        } else {
            const float* p = A2 + (size_t)(bm + rowA) * K2 + (kg - K1);
            ar0 = *reinterpret_cast<const float4*>(p);
            ar1 = *reinterpret_cast<const float4*>(p + 4);
        }
        const float* q = B + (size_t)(bn + rowB) * Bstr + (kc << 5) + kqB;
#pragma unroll
        for (int i = 0; i < 4; i++) br[i] = *reinterpret_cast<const float4*>(q + i * 4);
    };

    auto sts = [&](int buf) {
        const uint32_t base = sbase + (uint32_t)buf * STG_BYTES;
        {
            const uint32_t off = (uint32_t)(rowA * 16 + kw0s) * 4u;
            uint32_t h0, h1, h2, h3, l0, l1, l2, l3;
            splitbf(ar0.x, ar0.y, h0, l0); splitbf(ar0.z, ar0.w, h1, l1);
            splitbf(ar1.x, ar1.y, h2, l2); splitbf(ar1.z, ar1.w, h3, l3);
            sts128(base + OFF_AH * 4u + off, h0, h1, h2, h3);
            sts128(base + OFF_AL * 4u + off, l0, l1, l2, l3);
        }
        {
            uint32_t h[8], l[8];
#pragma unroll
            for (int i = 0; i < 4; i++) {
                splitbf(br[i].x, br[i].y, h[i * 2], l[i * 2]);
                splitbf(br[i].z, br[i].w, h[i * 2 + 1], l[i * 2 + 1]);
            }
            sts128(base + OFF_BH * 4u + offB0, h[0], h[1], h[2], h[3]);
            sts128(base + OFF_BH * 4u + offB1, h[4], h[5], h[6], h[7]);
            sts128(base + OFF_BL * 4u + offB0, l[0], l[1], l[2], l[3]);
            sts128(base + OFF_BL * 4u + offB1, l[4], l[5], l[6], l[7]);
        }
    };

    float acc[2][8][4];
#pragma unroll
    for (int i = 0; i < 2; i++)
#pragma unroll
        for (int j = 0; j < 8; j++)
#pragma unroll
            for (int r = 0; r < 4; r++) acc[i][j][r] = 0.f;

    ldg(0); sts(0);
    __syncthreads();
    ldg(1);

    const uint32_t* smw = reinterpret_cast<const uint32_t*>(sm);
    const int swzf = ((g >> 1) & 3) << 2;

    for (int k = 0; k < KC; k++) {
        if (k + 1 < KC) sts((k + 1) & 1);

        const uint32_t* S  = smw + (size_t)(k & 1) * STG_W;
        const uint32_t* AH = S + OFF_AH;
        const uint32_t* AL = S + OFF_AL;
        const uint32_t* BH = S + OFF_BH;
        const uint32_t* BL = S + OFF_BL;

#pragma unroll
        for (int ks = 0; ks < 2; ks++) {
            const int w0 = ((ks << 3) + c) ^ swzf;
            const int w1 = ((ks << 3) + 4 + c) ^ swzf;
            uint32_t aH[2][4], aL[2][4];
#pragma unroll
            for (int i = 0; i < 2; i++) {
                int r0 = (wm + (i << 4) + g) << 4;
                int r1 = r0 + (8 << 4);
                aH[i][0] = AH[r0 + w0]; aH[i][1] = AH[r1 + w0];
                aH[i][2] = AH[r0 + w1]; aH[i][3] = AH[r1 + w1];
                aL[i][0] = AL[r0 + w0]; aL[i][1] = AL[r1 + w0];
                aL[i][2] = AL[r0 + w1]; aL[i][3] = AL[r1 + w1];
            }
            // j-pairs: load B frags just-in-time, interleave with mma stream
#pragma unroll
            for (int jp = 0; jp < 4; jp++) {
                uint32_t bH[2][2], bL[2][2];
#pragma unroll
                for (int q = 0; q < 2; q++) {
                    int j = jp * 2 + q;
                    int r0 = (wn + (j << 3) + g) << 4;
                    bH[q][0] = BH[r0 + w0]; bH[q][1] = BH[r0 + w1];
                    bL[q][0] = BL[r0 + w0]; bL[q][1] = BL[r0 + w1];
                }
#pragma unroll
                for (int i = 0; i < 2; i++)
#pragma unroll
                    for (int q = 0; q < 2; q++) {
                        mma16(acc[i][jp * 2 + q], aH[i], bH[q]);
                        mma16(acc[i][jp * 2 + q], aL[i], bH[q]);
                        mma16(acc[i][jp * 2 + q], aH[i], bL[q]);
                    }
            }
        }
        if (k + 2 < KC) ldg(k + 2);
        __syncthreads();
    }

#pragma unroll
    for (int i = 0; i < 2; i++) {
        int row0 = bm + wm + (i << 4) + g;
        int row1 = row0 + 8;
#pragma unroll
        for (int j = 0; j < 8; j++) {
            int col = bn + wn + (j << 3) + (c << 1);
            float2 b2 = *reinterpret_cast<const float2*>(bias + col);
            float2 v0 = make_float2(acc[i][j][0] + b2.x, acc[i][j][1] + b2.y);
            float2 v1 = make_float2(acc[i][j][2] + b2.x, acc[i][j][3] + b2.y);
            *reinterpret_cast<float2*>(C + (size_t)row0 * Ntot + col) = v0;
            *reinterpret_cast<float2*>(C + (size_t)row1 * Ntot + col) = v1;
        }
    }
}

// ---------------- fp32 FFMA GEMM (fix path) ----------------
#define GBM 128
#define GBN 128
#define GBK 16
#define GTM 8
#define GTN 8

__global__ __launch_bounds__(256, 2)
void gemm_f32(const float* __restrict__ A1, int K1,
              const float* __restrict__ A2, int K2,
              const float* __restrict__ B,
              const float* __restrict__ bias,
              float* __restrict__ C, int N)
{
    __shared__ __align__(16) float As[GBK][GBM];
    __shared__ __align__(16) float Bs[GBK][GBN];
    const int K  = K1 + K2;
    const int bm = blockIdx.y * GBM;
    const int bn = blockIdx.x * GBN;
    const int t  = threadIdx.x;
    const int tx = t & 15;
    const int ty = t >> 4;

    float acc[GTM][GTN];
#pragma unroll
    for (int i = 0; i < GTM; i++)
#pragma unroll
        for (int j = 0; j < GTN; j++) acc[i][j] = 0.f;

    for (int kt = 0; kt < K; kt += GBK) {
#pragma unroll
        for (int q = 0; q < 2; q++) {
            int li  = t * 2 + q;
            int row = li >> 2;
            int kq  = (li & 3) << 2;
            int kg  = kt + kq;
            {
                int m = bm + row;
                float4 v;
                if (kg < K1) v = *reinterpret_cast<const float4*>(A1 + (size_t)m * K1 + kg);
                else         v = *reinterpret_cast<const float4*>(A2 + (size_t)m * K2 + (kg - K1));
                As[kq + 0][row] = v.x; As[kq + 1][row] = v.y;
                As[kq + 2][row] = v.z; As[kq + 3][row] = v.w;
            }
            {
                int n = bn + row;
                float4 w = *reinterpret_cast<const float4*>(B + (size_t)n * K + kg);
                Bs[kq + 0][row] = w.x; Bs[kq + 1][row] = w.y;
                Bs[kq + 2][row] = w.z; Bs[kq + 3][row] = w.w;
            }
        }
        __syncthreads();
#pragma unroll
        for (int k = 0; k < GBK; k++) {
            float4 a0 = *reinterpret_cast<const float4*>(&As[k][ty * GTM]);
            float4 a1 = *reinterpret_cast<const float4*>(&As[k][ty * GTM + 4]);
            float4 b0 = *reinterpret_cast<const float4*>(&Bs[k][tx * GTN]);
            float4 b1 = *reinterpret_cast<const float4*>(&Bs[k][tx * GTN + 4]);
            float a[8] = {a0.x, a0.y, a0.z, a0.w, a1.x, a1.y, a1.z, a1.w};
            float b[8] = {b0.x, b0.y, b0.z, b0.w, b1.x, b1.y, b1.z, b1.w};
#pragma unroll
            for (int i = 0; i < GTM; i++)
#pragma unroll
                for (int j = 0; j < GTN; j++)
                    acc[i][j] = fmaf(a[i], b[j], acc[i][j]);
        }
        __syncthreads();
    }
#pragma unroll
    for (int i = 0; i < GTM; i++) {
        int m = bm + ty * GTM + i;
        float* crow = C + (size_t)m * N + bn + tx * GTN;
#pragma unroll
        for (int j = 0; j < GTN; j++)
            crow[j] = acc[i][j] + bias[bn + tx * GTN + j];
    }
}

// ---------------- GRU elementwise combine ----------------
__global__ void gru_kernel(const float* __restrict__ deter,
                           const unsigned char* __restrict__ first,
                           float* __restrict__ h_out)
{
    int i = blockIdx.x * blockDim.x + threadIdx.x;
    if (i >= BSZ * REC) return;
    int m = i >> 10;
    int n = i & 1023;
    size_t base = (size_t)m * (3 * REC) + n;
    float ir  = g_gi[base];
    float iz  = g_gi[base + REC];
    float i_n = g_gi[base + 2 * REC];
    float hr  = g_gh[base];
    float hz  = g_gh[base + REC];
    float h_n = g_gh[base + 2 * REC];
    float d = first[m] ? 0.f : deter[i];
    float r  = 1.f / (1.f + expf(-(ir + hr)));
    float z  = 1.f / (1.f + expf(-(iz + hz)));
    float nn = tanhf(i_n + r * h_n);
    h_out[i] = (1.f - z) * nn + z * d;
}

// ---------------- threefry2x32 + gumbel ----------------
__device__ __forceinline__ uint32_t threefry_bits(uint32_t x1in)
{
    const uint32_t ks0 = 0u;
    const uint32_t ks1 = 42u;
    const uint32_t ks2 = 0x1BD11BDAu ^ ks0 ^ ks1;
    uint32_t x0 = 0u + ks0;
    uint32_t x1 = x1in + ks1;
#define TF_R(r) { x0 += x1; x1 = __funnelshift_l(x1, x1, (r)); x1 ^= x0; }
    TF_R(13) TF_R(15) TF_R(26) TF_R(6)
    x0 += ks1; x1 += ks2 + 1u;
    TF_R(17) TF_R(29) TF_R(16) TF_R(24)
    x0 += ks2; x1 += ks0 + 2u;
    TF_R(13) TF_R(15) TF_R(26) TF_R(6)
    x0 += ks0; x1 += ks1 + 3u;
    TF_R(17) TF_R(29) TF_R(16) TF_R(24)
    x0 += ks1; x1 += ks2 + 4u;
    TF_R(13) TF_R(15) TF_R(26) TF_R(6)
    x0 += ks2; x1 += ks0 + 5u;
#undef TF_R
    return x0 ^ x1;
}

__device__ __forceinline__ float gumbel_at(uint32_t idx)
{
    uint32_t bits = threefry_bits(idx);
    float f = __uint_as_float((bits >> 9) | 0x3f800000u) - 1.0f;
    float u = fmaxf(f, 1.17549435e-38f);
    float inner = -logf(u);
    return -__logf(inner);
}

__global__ void sample_kernel(const float* __restrict__ logits,
                              float* __restrict__ stoch_out)
{
    int g = blockIdx.x * blockDim.x + threadIdx.x;
    if (g >= BSZ * 32) return;
    const float4* lrow = reinterpret_cast<const float4*>(logits + (size_t)g * 32);
    float best = -3.4e38f, second = -3.4e38f;
    int   bi   = 0;
    uint32_t base = (uint32_t)g * 32u;
#pragma unroll
    for (int q = 0; q < 8; q++) {
        float4 lv = lrow[q];
        float l4[4] = {lv.x, lv.y, lv.z, lv.w};
#pragma unroll
        for (int ci = 0; ci < 4; ci++) {
            int d = q * 4 + ci;
            float s = l4[ci] + gumbel_at(base + (uint32_t)d);
            if (s > best) { second = best; best = s; bi = d; }
            else if (s > second) second = s;
        }
    }
    float4* dst = reinterpret_cast<float4*>(stoch_out + (size_t)g * 32);
#pragma unroll
    for (int q = 0; q < 8; q++) {
        float4 v;
        v.x = (bi == q * 4 + 0) ? 1.f : 0.f;
        v.y = (bi == q * 4 + 1) ? 1.f : 0.f;
        v.z = (bi == q * 4 + 2) ? 1.f : 0.f;
        v.w = (bi == q * 4 + 3) ? 1.f : 0.f;
        dst[q] = v;
    }
    if (best - second < FIX_TAU) {
        int slot = atomicAdd(&g_namb, 1);
        if (slot < AMB_CAP) g_amb[slot] = g;
    }
}

// ---------------- fix path ----------------
__global__ void init_fix()
{
    int t = blockIdx.x * blockDim.x + threadIdx.x;
    if (t == 0) { g_namb = 0; g_nrows = 0; }
    for (int i = t; i < BSZ; i += gridDim.x * blockDim.x) g_rowflag[i] = 0;
}

__global__ void gather_rows(const float* __restrict__ stoch,
                            const float* __restrict__ deter,
                            const float* __restrict__ action,
                            const float* __restrict__ obs,
                            const unsigned char* __restrict__ first)
{
    __shared__ int s_row, s_slot;
    int namb = min(g_namb, AMB_CAP);
    for (int e = blockIdx.x; e < namb; e += gridDim.x) {
        if (threadIdx.x == 0) {
            int row = g_amb[e] >> 5;
            int slot = -1;
            if (atomicExch(&g_rowflag[row], 1) == 0) {
                int s = atomicAdd(&g_nrows, 1);
                if (s < FIX_ROWS) { g_rowlist[s] = row; slot = s; }
            }
            s_row = row; s_slot = slot;
        }
        __syncthreads();
        int slot = s_slot, row = s_row;
        if (slot >= 0) {
            bool f = first[row] != 0;
            for (int j = threadIdx.x; j < SDIM; j += blockDim.x)
                g_fin[(size_t)slot * 1088 + j] = f ? 0.f : stoch[(size_t)row * SDIM + j];
            for (int j = threadIdx.x; j < ADIM; j += blockDim.x)
                g_fin[(size_t)slot * 1088 + SDIM + j] = action[(size_t)row * ADIM + j];
            for (int j = threadIdx.x; j < REC; j += blockDim.x)
                g_fdet[(size_t)slot * 1024 + j] = f ? 0.f : deter[(size_t)row * REC + j];
            for (int j = threadIdx.x; j < HID; j += blockDim.x)
                g_fobs[(size_t)slot * 1024 + j] = obs[(size_t)row * HID + j];
        }
        __syncthreads();
    }
}

__global__ void fgru_kernel()
{
    int i = blockIdx.x * blockDim.x + threadIdx.x;
    if (i >= FIX_ROWS * 1024) return;
    int r = i >> 10, n = i & 1023;
    size_t base = (size_t)r * 3072 + n;
    float ir  = g_fgi[base];
    float iz  = g_fgi[base + 1024];
    float i_n = g_fgi[base + 2048];
    float hr  = g_fgh[base];
    float hz  = g_fgh[base + 1024];
    float h_n = g_fgh[base + 2048];
    float d = g_fdet[i];
    float rr = 1.f / (1.f + expf(-(ir + hr)));
    float zz = 1.f / (1.f + expf(-(iz + hz)));
    float nn = tanhf(i_n + rr * h_n);
    g_fh[i] = (1.f - zz) * nn + zz * d;
}

__global__ void fix_sample(float* __restrict__ stoch_out)
{
    int idx = blockIdx.x * blockDim.x + threadIdx.x;
    int r = idx >> 5, gl = idx & 31;
    if (r >= min(g_nrows, FIX_ROWS)) return;
    int row = g_rowlist[r];
    const float* l = g_flog + (size_t)r * 1024 + gl * 32;
    uint32_t base = ((uint32_t)row * 32u + (uint32_t)gl) * 32u;
    float best = -3.4e38f;
    int bi = 0;
#pragma unroll
    for (int d = 0; d < 32; d++) {
        float s = l[d] + gumbel_at(base + (uint32_t)d);
        if (s > best) { best = s; bi = d; }
    }
    float* dst = stoch_out + (size_t)row * 1024 + gl * 32;
#pragma unroll
    for (int d = 0; d < 32; d++) dst[d] = (d == bi) ? 1.f : 0.f;
}

// ---------------- launch ----------------
extern "C" void kernel_launch(void* const* d_in, const int* in_sizes, int n_in,
                              void* d_out, int out_size)
{
    (void)in_sizes; (void)n_in; (void)out_size;
    const float* stoch  = (const float*)d_in[0];
    const float* deter  = (const float*)d_in[1];
    const float* action = (const float*)d_in[3];
    const float* obs    = (const float*)d_in[4];
    const unsigned char* first = (const unsigned char*)d_in[5];
    const float* W_in   = (const float*)d_in[6];
    const float* b_in   = (const float*)d_in[7];
    const float* W_ih   = (const float*)d_in[8];
    const float* b_ih   = (const float*)d_in[9];
    const float* W_hh   = (const float*)d_in[10];
    const float* b_hh   = (const float*)d_in[11];
    const float* W_post = (const float*)d_in[14];
    const float* b_post = (const float*)d_in[15];

    float* out        = (float*)d_out;
    float* h_out      = out;
    float* stoch_out  = out + (size_t)BSZ * LATD;
    float* logits_out = out + 2 * (size_t)BSZ * LATD;

    float *gip, *ghp, *wt, *wc, *bc, *zb;
    float *fin, *fdet, *fobs, *fx, *fgi, *fgh, *fh, *flog;
    cudaGetSymbolAddress((void**)&gip, g_gi);
    cudaGetSymbolAddress((void**)&ghp, g_gh);
    cudaGetSymbolAddress((void**)&wt,  g_wt);
    cudaGetSymbolAddress((void**)&wc,  g_wc);
    cudaGetSymbolAddress((void**)&bc,  g_bc);
    cudaGetSymbolAddress((void**)&zb,  g_zb);
    cudaGetSymbolAddress((void**)&fin,  g_fin);
    cudaGetSymbolAddress((void**)&fdet, g_fdet);
    cudaGetSymbolAddress((void**)&fobs, g_fobs);
    cudaGetSymbolAddress((void**)&fx,   g_fx);
    cudaGetSymbolAddress((void**)&fgi,  g_fgi);
    cudaGetSymbolAddress((void**)&fgh,  g_fgh);
    cudaGetSymbolAddress((void**)&fh,   g_fh);
    cudaGetSymbolAddress((void**)&flog, g_flog);

    cudaFuncSetAttribute(mma_gemm, cudaFuncAttributeMaxDynamicSharedMemorySize, SMEM_CA);

    dim3 thr(MMA_THR);

    init_fix<<<64, 256>>>();
    // prep: W_in^T (padded) ; b_comb ; W_comb = W_ih @ W_in
    transpose_win<<<dim3(1280 / 32, 1024 / 32), dim3(32, 8)>>>(W_in);
    bcomb_kernel<<<3072 / 8, 256>>>(W_ih, b_in, b_ih);
    mma_gemm<<<dim3(1280 / 256, 3072 / 128), thr, SMEM_CA>>>(
        W_ih, 1024, W_ih, 0, nullptr, wt, 1024, zb, wc, 1280);

    // ---- main bf16x2-split path (GEMM1 fused away) ----
    // gi = [stoch*(~first), action] @ W_comb^T + b_comb    (K=1088, N=3072)
    mma_gemm<<<dim3(3072 / 256, BSZ / 128), thr, SMEM_CA>>>(
        stoch, SDIM, action, ADIM, first, wc, 1280, bc, gip, 3 * REC);
    // gh = deter*(~first) @ W_hh^T + b_hh                  (K=1024, N=3072)
    mma_gemm<<<dim3(3072 / 256, BSZ / 128), thr, SMEM_CA>>>(
        deter, REC, deter, 0, first, W_hh, 1024, b_hh, ghp, 3 * REC);
    gru_kernel<<<(BSZ * REC) / 256, 256>>>(deter, first, h_out);
    // logits = [h, obs] @ W_post^T + b_post                (K=2048, N=1024)
    mma_gemm<<<dim3(1024 / 256, BSZ / 128), thr, SMEM_CA>>>(
        h_out, REC, obs, HID, nullptr, W_post, 2048, b_post, logits_out, LATD);
    sample_kernel<<<(BSZ * 32) / 256, 256>>>(logits_out, stoch_out);

    // ---- fp32 fix path for near-tie groups (exact weights) ----
    gather_rows<<<256, 256>>>(stoch, deter, action, obs, first);
    gemm_f32<<<dim3(HID / GBN, FIX_ROWS / GBM), dim3(256)>>>(
        fin, 1088, fin, 0, W_in, b_in, fx, HID);
    gemm_f32<<<dim3(3 * REC / GBN, FIX_ROWS / GBM), dim3(256)>>>(
        fx, 1024, fx, 0, W_ih, b_ih, fgi, 3 * REC);
    gemm_f32<<<dim3(3 * REC / GBN, FIX_ROWS / GBM), dim3(256)>>>(
        fdet, 1024, fdet, 0, W_hh, b_hh, fgh, 3 * REC);
    fgru_kernel<<<(FIX_ROWS * 1024) / 256, 256>>>();
    gemm_f32<<<dim3(LATD / GBN, FIX_ROWS / GBM), dim3(256)>>>(
        fh, 1024, fobs, 1024, W_post, b_post, flog, LATD);
    fix_sample<<<(FIX_ROWS * 32) / 256, 256>>>(stoch_out);
}

// round 14
// speedup vs baseline: 1.1520x; 1.0629x over previous
#include <cuda_runtime.h>
#include <cuda_bf16.h>
#include <cstdint>
#include <cstddef>

#define BSZ  16384
#define SDIM 1024
#define ADIM 64
#define HID  1024
#define REC  1024
#define LATD 1024

// f32 scratch
__device__ float g_gi[(size_t)BSZ * 3 * REC];
__device__ float g_gh[(size_t)BSZ * 3 * REC];
__device__ float g_wt[(size_t)1280 * 1024];   // W_in^T padded (rows>=1088 zero)
__device__ float g_wc[(size_t)3072 * 1280];   // W_comb f32
__device__ float g_bc[3072];
__device__ float g_zb[1280];

// bf16 pre-split operand arrays (hi/lo)
__device__ __nv_bfloat16 g_act_h[(size_t)BSZ * 1088], g_act_l[(size_t)BSZ * 1088];
__device__ __nv_bfloat16 g_det_h[(size_t)BSZ * 1024], g_det_l[(size_t)BSZ * 1024];
__device__ __nv_bfloat16 g_ho_h [(size_t)BSZ * 2048], g_ho_l [(size_t)BSZ * 2048];
__device__ __nv_bfloat16 g_wih_h[(size_t)3072 * 1024], g_wih_l[(size_t)3072 * 1024];
__device__ __nv_bfloat16 g_wt_h [(size_t)1280 * 1024], g_wt_l [(size_t)1280 * 1024];
__device__ __nv_bfloat16 g_wc_h [(size_t)3072 * 1088], g_wc_l [(size_t)3072 * 1088];
__device__ __nv_bfloat16 g_whh_h[(size_t)3072 * 1024], g_whh_l[(size_t)3072 * 1024];
__device__ __nv_bfloat16 g_wp_h [(size_t)1024 * 2048], g_wp_l [(size_t)1024 * 2048];

// ---- ambiguous-group fix machinery ----
#define FIX_TAU  2e-4f
#define AMB_CAP  16384
#define FIX_ROWS 512
__device__ int   g_namb;
__device__ int   g_nrows;
__device__ int   g_amb[AMB_CAP];
__device__ int   g_rowlist[FIX_ROWS];
__device__ int   g_rowflag[BSZ];
__device__ float g_fin [(size_t)FIX_ROWS * 1088];
__device__ float g_fdet[(size_t)FIX_ROWS * 1024];
__device__ float g_fobs[(size_t)FIX_ROWS * 1024];
__device__ float g_fx  [(size_t)FIX_ROWS * 1024];
__device__ float g_fgi [(size_t)FIX_ROWS * 3072];
__device__ float g_fgh [(size_t)FIX_ROWS * 3072];
__device__ float g_fh  [(size_t)FIX_ROWS * 1024];
__device__ float g_flog[(size_t)FIX_ROWS * 1024];

__device__ __forceinline__ uint32_t smem_u32(const void* p) {
    uint32_t a;
    asm("{ .reg .u64 t; cvta.to.shared.u64 t, %1; cvt.u32.u64 %0, t; }"
        : "=r"(a) : "l"(p));
    return a;
}
__device__ __forceinline__ void splitbf(float x0, float x1, uint32_t& hi, uint32_t& lo) {
    uint32_t u0 = __float_as_uint(x0), u1 = __float_as_uint(x1);
    uint32_t h;
    asm("prmt.b32 %0, %1, %2, 0x7632;" : "=r"(h) : "r"(u0), "r"(u1));
    hi = h;
    float f0 = __uint_as_float(u0 & 0xFFFF0000u);
    float f1 = __uint_as_float(u1 & 0xFFFF0000u);
    float r0 = x0 - f0;
    float r1 = x1 - f1;
    asm("cvt.rn.bf16x2.f32 %0, %1, %2;" : "=r"(lo) : "f"(r1), "f"(r0));
}

// ---------------- generic split kernel (f32 -> bf16 hi/lo) ----------------
// row r in [0,rows), col j in [0,K1+K2): val = j<K1 ? (mask? 0 : src[r*srcStride+j])
//                                              : src2[r*K2 + (j-K1)]
__global__ void split_kernel(const float* __restrict__ src, int srcStride,
                             const float* __restrict__ src2, int K1, int K2,
                             const unsigned char* __restrict__ mask,
                             __nv_bfloat16* __restrict__ hi,
                             __nv_bfloat16* __restrict__ lo,
                             int rows)
{
    const int Kd = K1 + K2;
    size_t e = ((size_t)blockIdx.x * blockDim.x + threadIdx.x) * 4;
    if (e >= (size_t)rows * Kd) return;
    int r = (int)(e / Kd);
    int j = (int)(e % Kd);
    float4 v;
    if (j < K1) {
        if (mask != nullptr && mask[r]) v = make_float4(0.f, 0.f, 0.f, 0.f);
        else v = *reinterpret_cast<const float4*>(src + (size_t)r * srcStride + j);
    } else {
        v = *reinterpret_cast<const float4*>(src2 + (size_t)r * K2 + (j - K1));
    }
    uint32_t h0, h1, l0, l1;
    splitbf(v.x, v.y, h0, l0);
    splitbf(v.z, v.w, h1, l1);
    size_t d = (size_t)r * Kd + j;
    *reinterpret_cast<uint2*>(hi + d) = make_uint2(h0, h1);
    *reinterpret_cast<uint2*>(lo + d) = make_uint2(l0, l1);
}

// ---------------- prep kernels ----------------
__global__ void transpose_win(const float* __restrict__ W_in)
{
    __shared__ float tile[32][33];
    int j0 = blockIdx.x << 5, h0 = blockIdx.y << 5;
    int tx = threadIdx.x, ty = threadIdx.y;
#pragma unroll
    for (int i = 0; i < 4; i++) {
        int h = h0 + ty + i * 8, j = j0 + tx;
        tile[ty + i * 8][tx] = (j < SDIM + ADIM) ? W_in[(size_t)h * (SDIM + ADIM) + j] : 0.f;
    }
    __syncthreads();
#pragma unroll
    for (int i = 0; i < 4; i++) {
        int j = j0 + ty + i * 8, h = h0 + tx;
        g_wt[(size_t)j * 1024 + h] = tile[tx][ty + i * 8];
    }
}

__global__ void bcomb_kernel(const float* __restrict__ W_ih,
                             const float* __restrict__ b_in,
                             const float* __restrict__ b_ih)
{
    int n = blockIdx.x * (blockDim.x >> 5) + (threadIdx.x >> 5);
    if (n >= 3072) return;
    int lane = threadIdx.x & 31;
    float s = 0.f;
    const float* row = W_ih + (size_t)n * 1024;
    for (int h = lane; h < 1024; h += 32) s += row[h] * b_in[h];
#pragma unroll
    for (int o = 16; o; o >>= 1) s += __shfl_xor_sync(0xFFFFFFFFu, s, o);
    if (lane == 0) g_bc[n] = s + b_ih[n];
}

// ---------------- bf16 hi/lo GEMM: cp.async + LDS frags + mma ----------------
// C[m,n] = bias[n] + sum_k (Ah+Al)[m,k]*(Bh+Bl)[n,k] (hh+lh+hl terms)
// CTA 128x256, 512 thr (16 warps 4x4), warp tile 32x64, K-chunk 32.
// Smem comp: A 128 rows x 64B, B 256 rows x 64B; 16B chunk q swizzled: q^((r>>1)&3).
#define MMA_THR 512
#define STG_BYTES 49152                       // 8K Ah + 8K Al + 16K Bh + 16K Bl
#define NSTAGE 3
#define SMEM_CA  (NSTAGE * STG_BYTES)         // 147456
#define OFFB_AH 0
#define OFFB_AL 8192
#define OFFB_BH 16384
#define OFFB_BL 32768

__device__ __forceinline__ void mma16(float c[4], const uint32_t a[4], const uint32_t b[2]) {
    asm volatile("mma.sync.aligned.m16n8k16.row.col.f32.bf16.bf16.f32 "
                 "{%0,%1,%2,%3}, {%4,%5,%6,%7}, {%8,%9}, {%0,%1,%2,%3};"
                 : "+f"(c[0]), "+f"(c[1]), "+f"(c[2]), "+f"(c[3])
                 : "r"(a[0]), "r"(a[1]), "r"(a[2]), "r"(a[3]), "r"(b[0]), "r"(b[1]));
}
__device__ __forceinline__ void cp16(uint32_t dst, const void* src) {
    asm volatile("cp.async.cg.shared.global [%0], [%1], 16;"
                 :: "r"(dst), "l"(src) : "memory");
}
#define CP_COMMIT() asm volatile("cp.async.commit_group;" ::: "memory")
#define CP_WAIT1()  asm volatile("cp.async.wait_group 1;" ::: "memory")

__global__ __launch_bounds__(MMA_THR, 1)
void bfgemm(const __nv_bfloat16* __restrict__ Ah, const __nv_bfloat16* __restrict__ Al,
            const __nv_bfloat16* __restrict__ Bh, const __nv_bfloat16* __restrict__ Bl,
            const float* __restrict__ bias, float* __restrict__ C,
            int Ntot, int K)
{
    extern __shared__ __align__(16) char smc[];
    const uint32_t sbase = smem_u32(smc);
    const uint32_t* smw = reinterpret_cast<const uint32_t*>(smc);

    const int KC = K >> 5;
    const int bm = blockIdx.y << 7;
    const int bn = blockIdx.x << 8;
    const int t  = threadIdx.x;
    const int wid  = t >> 5;
    const int lane = t & 31;
    const int g = lane >> 2;
    const int c = lane & 3;
    const int wm = (wid >> 2) << 5;
    const int wn = (wid & 3) << 6;

    // copy mapping: A one hi + one lo chunk at (rowA=t>>2, q=t&3);
    // B four chunks: ids t, t+512 (hi rows 0..255), same for lo.
    const int rowA = t >> 2;
    const int qA   = t & 3;
    const uint32_t dA = (uint32_t)(rowA * 64 + ((qA ^ ((rowA >> 1) & 3)) << 4));
    const int rB0 = t >> 2, rB1 = (t + 512) >> 2;
    const int qB0 = t & 3,  qB1 = qB0;
    const uint32_t dB0 = (uint32_t)(rB0 * 64 + ((qB0 ^ ((rB0 >> 1) & 3)) << 4));
    const uint32_t dB1 = (uint32_t)(rB1 * 64 + ((qB1 ^ ((rB1 >> 1) & 3)) << 4));

    auto issue_stage = [&](int kc) {
        if (kc < KC) {
            const uint32_t st = sbase + (uint32_t)(kc % NSTAGE) * STG_BYTES;
            const int ke = (kc << 5) + (qA << 3);   // bf16 elem offset (8 per 16B)
            cp16(st + OFFB_AH + dA, Ah + (size_t)(bm + rowA) * K + ke);
            cp16(st + OFFB_AL + dA, Al + (size_t)(bm + rowA) * K + ke);
            cp16(st + OFFB_BH + dB0, Bh + (size_t)(bn + rB0) * K + ke);
            cp16(st + OFFB_BH + dB1, Bh + (size_t)(bn + rB1) * K + ke);
            cp16(st + OFFB_BL + dB0, Bl + (size_t)(bn + rB0) * K + ke);
            cp16(st + OFFB_BL + dB1, Bl + (size_t)(bn + rB1) * K + ke);
        }
        CP_COMMIT();
    };

    float acc[2][8][4];
#pragma unroll
    for (int i = 0; i < 2; i++)
#pragma unroll
        for (int j = 0; j < 8; j++)
#pragma unroll
            for (int r = 0; r < 4; r++) acc[i][j][r] = 0.f;

    issue_stage(0);
    issue_stage(1);

    const int swzf = ((g >> 1) & 3) << 2;

    for (int k = 0; k < KC; k++) {
        CP_WAIT1();
        __syncthreads();
        issue_stage(k + 2);

        const uint32_t* S  = smw + (size_t)(k % NSTAGE) * (STG_BYTES / 4);
        const uint32_t* AH = S;
        const uint32_t* AL = S + OFFB_AL / 4;
        const uint32_t* BH = S + OFFB_BH / 4;
        const uint32_t* BL = S + OFFB_BL / 4;

#pragma unroll
        for (int ks = 0; ks < 2; ks++) {
            const int w0 = ((ks << 3) + c) ^ swzf;
            const int w1 = ((ks << 3) + 4 + c) ^ swzf;
            uint32_t aH[2][4], aL[2][4];
#pragma unroll
            for (int i = 0; i < 2; i++) {
                int r0 = (wm + (i << 4) + g) << 4;
                int r1 = r0 + (8 << 4);
                aH[i][0] = AH[r0 + w0]; aH[i][1] = AH[r1 + w0];
                aH[i][2] = AH[r0 + w1]; aH[i][3] = AH[r1 + w1];
                aL[i][0] = AL[r0 + w0]; aL[i][1] = AL[r1 + w0];
                aL[i][2] = AL[r0 + w1]; aL[i][3] = AL[r1 + w1];
            }
#pragma unroll
            for (int jp = 0; jp < 4; jp++) {
                uint32_t bH[2][2], bL[2][2];
#pragma unroll
                for (int q = 0; q < 2; q++) {
                    int j = jp * 2 + q;
                    int r0 = (wn + (j << 3) + g) << 4;
                    bH[q][0] = BH[r0 + w0]; bH[q][1] = BH[r0 + w1];
                    bL[q][0] = BL[r0 + w0]; bL[q][1] = BL[r0 + w1];
                }
#pragma unroll
                for (int i = 0; i < 2; i++)
#pragma unroll
                    for (int q = 0; q < 2; q++) {
                        mma16(acc[i][jp * 2 + q], aH[i], bH[q]);
                        mma16(acc[i][jp * 2 + q], aL[i], bH[q]);
                        mma16(acc[i][jp * 2 + q], aH[i], bL[q]);
                    }
            }
        }
        __syncthreads();
    }

#pragma unroll
    for (int i = 0; i < 2; i++) {
        int row0 = bm + wm + (i << 4) + g;
        int row1 = row0 + 8;
#pragma unroll
        for (int j = 0; j < 8; j++) {
            int col = bn + wn + (j << 3) + (c << 1);
            float2 b2 = *reinterpret_cast<const float2*>(bias + col);
            float2 v0 = make_float2(acc[i][j][0] + b2.x, acc[i][j][1] + b2.y);
            float2 v1 = make_float2(acc[i][j][2] + b2.x, acc[i][j][3] + b2.y);
            *reinterpret_cast<float2*>(C + (size_t)row0 * Ntot + col) = v0;
            *reinterpret_cast<float2*>(C + (size_t)row1 * Ntot + col) = v1;
        }
    }
}

// ---------------- fp32 FFMA GEMM (fix path) ----------------
#define GBM 128
#define GBN 128
#define GBK 16
#define GTM 8
#define GTN 8

__global__ __launch_bounds__(256, 2)
void gemm_f32(const float* __restrict__ A1, int K1,
              const float* __restrict__ A2, int K2,
              const float* __restrict__ B,
              const float* __restrict__ bias,
              float* __restrict__ C, int N)
{
    __shared__ __align__(16) float As[GBK][GBM];
    __shared__ __align__(16) float Bs[GBK][GBN];
    const int K  = K1 + K2;
    const int bm = blockIdx.y * GBM;
    const int bn = blockIdx.x * GBN;
    const int t  = threadIdx.x;
    const int tx = t & 15;
    const int ty = t >> 4;

    float acc[GTM][GTN];
#pragma unroll
    for (int i = 0; i < GTM; i++)
#pragma unroll
        for (int j = 0; j < GTN; j++) acc[i][j] = 0.f;

    for (int kt = 0; kt < K; kt += GBK) {
#pragma unroll
        for (int q = 0; q < 2; q++) {
            int li  = t * 2 + q;
            int row = li >> 2;
            int kq  = (li & 3) << 2;
            int kg  = kt + kq;
            {
                int m = bm + row;
                float4 v;
                if (kg < K1) v = *reinterpret_cast<const float4*>(A1 + (size_t)m * K1 + kg);
                else         v = *reinterpret_cast<const float4*>(A2 + (size_t)m * K2 + (kg - K1));
                As[kq + 0][row] = v.x; As[kq + 1][row] = v.y;
                As[kq + 2][row] = v.z; As[kq + 3][row] = v.w;
            }
            {
                int n = bn + row;
                float4 w = *reinterpret_cast<const float4*>(B + (size_t)n * K + kg);
                Bs[kq + 0][row] = w.x; Bs[kq + 1][row] = w.y;
                Bs[kq + 2][row] = w.z; Bs[kq + 3][row] = w.w;
            }
        }
        __syncthreads();
#pragma unroll
        for (int k = 0; k < GBK; k++) {
            float4 a0 = *reinterpret_cast<const float4*>(&As[k][ty * GTM]);
            float4 a1 = *reinterpret_cast<const float4*>(&As[k][ty * GTM + 4]);
            float4 b0 = *reinterpret_cast<const float4*>(&Bs[k][tx * GTN]);
            float4 b1 = *reinterpret_cast<const float4*>(&Bs[k][tx * GTN + 4]);
            float a[8] = {a0.x, a0.y, a0.z, a0.w, a1.x, a1.y, a1.z, a1.w};
            float b[8] = {b0.x, b0.y, b0.z, b0.w, b1.x, b1.y, b1.z, b1.w};
#pragma unroll
            for (int i = 0; i < GTM; i++)
#pragma unroll
                for (int j = 0; j < GTN; j++)
                    acc[i][j] = fmaf(a[i], b[j], acc[i][j]);
        }
        __syncthreads();
    }
#pragma unroll
    for (int i = 0; i < GTM; i++) {
        int m = bm + ty * GTM + i;
        float* crow = C + (size_t)m * N + bn + tx * GTN;
#pragma unroll
        for (int j = 0; j < GTN; j++)
            crow[j] = acc[i][j] + bias[bn + tx * GTN + j];
    }
}

// ---------------- GRU elementwise combine ----------------
__global__ void gru_kernel(const float* __restrict__ deter,
                           const unsigned char* __restrict__ first,
                           float* __restrict__ h_out)
{
    int i = blockIdx.x * blockDim.x + threadIdx.x;
    if (i >= BSZ * REC) return;
    int m = i >> 10;
    int n = i & 1023;
    size_t base = (size_t)m * (3 * REC) + n;
    float ir  = g_gi[base];
    float iz  = g_gi[base + REC];
    float i_n = g_gi[base + 2 * REC];
    float hr  = g_gh[base];
    float hz  = g_gh[base + REC];
    float h_n = g_gh[base + 2 * REC];
    float d = first[m] ? 0.f : deter[i];
    float r  = 1.f / (1.f + expf(-(ir + hr)));
    float z  = 1.f / (1.f + expf(-(iz + hz)));
    float nn = tanhf(i_n + r * h_n);
    h_out[i] = (1.f - z) * nn + z * d;
}

// ---------------- threefry2x32 + gumbel ----------------
__device__ __forceinline__ uint32_t threefry_bits(uint32_t x1in)
{
    const uint32_t ks0 = 0u;
    const uint32_t ks1 = 42u;
    const uint32_t ks2 = 0x1BD11BDAu ^ ks0 ^ ks1;
    uint32_t x0 = 0u + ks0;
    uint32_t x1 = x1in + ks1;
#define TF_R(r) { x0 += x1; x1 = __funnelshift_l(x1, x1, (r)); x1 ^= x0; }
    TF_R(13) TF_R(15) TF_R(26) TF_R(6)
    x0 += ks1; x1 += ks2 + 1u;
    TF_R(17) TF_R(29) TF_R(16) TF_R(24)
    x0 += ks2; x1 += ks0 + 2u;
    TF_R(13) TF_R(15) TF_R(26) TF_R(6)
    x0 += ks0; x1 += ks1 + 3u;
    TF_R(17) TF_R(29) TF_R(16) TF_R(24)
    x0 += ks1; x1 += ks2 + 4u;
    TF_R(13) TF_R(15) TF_R(26) TF_R(6)
    x0 += ks2; x1 += ks0 + 5u;
#undef TF_R
    return x0 ^ x1;
}

__device__ __forceinline__ float gumbel_at(uint32_t idx)
{
    uint32_t bits = threefry_bits(idx);
    float f = __uint_as_float((bits >> 9) | 0x3f800000u) - 1.0f;
    float u = fmaxf(f, 1.17549435e-38f);
    float inner = -logf(u);
    return -__logf(inner);
}

__global__ void sample_kernel(const float* __restrict__ logits,
                              float* __restrict__ stoch_out)
{
    int g = blockIdx.x * blockDim.x + threadIdx.x;
    if (g >= BSZ * 32) return;
    const float4* lrow = reinterpret_cast<const float4*>(logits + (size_t)g * 32);
    float best = -3.4e38f, second = -3.4e38f;
    int   bi   = 0;
    uint32_t base = (uint32_t)g * 32u;
#pragma unroll
    for (int q = 0; q < 8; q++) {
        float4 lv = lrow[q];
        float l4[4] = {lv.x, lv.y, lv.z, lv.w};
#pragma unroll
        for (int ci = 0; ci < 4; ci++) {
            int d = q * 4 + ci;
            float s = l4[ci] + gumbel_at(base + (uint32_t)d);
            if (s > best) { second = best; best = s; bi = d; }
            else if (s > second) second = s;
        }
    }
    float4* dst = reinterpret_cast<float4*>(stoch_out + (size_t)g * 32);
#pragma unroll
    for (int q = 0; q < 8; q++) {
        float4 v;
        v.x = (bi == q * 4 + 0) ? 1.f : 0.f;
        v.y = (bi == q * 4 + 1) ? 1.f : 0.f;
        v.z = (bi == q * 4 + 2) ? 1.f : 0.f;
        v.w = (bi == q * 4 + 3) ? 1.f : 0.f;
        dst[q] = v;
    }
    if (best - second < FIX_TAU) {
        int slot = atomicAdd(&g_namb, 1);
        if (slot < AMB_CAP) g_amb[slot] = g;
    }
}

// ---------------- fix path ----------------
__global__ void init_fix()
{
    int t = blockIdx.x * blockDim.x + threadIdx.x;
    if (t == 0) { g_namb = 0; g_nrows = 0; }
    for (int i = t; i < BSZ; i += gridDim.x * blockDim.x) g_rowflag[i] = 0;
}

__global__ void gather_rows(const float* __restrict__ stoch,
                            const float* __restrict__ deter,
                            const float* __restrict__ action,
                            const float* __restrict__ obs,
                            const unsigned char* __restrict__ first)
{
    __shared__ int s_row, s_slot;
    int namb = min(g_namb, AMB_CAP);
    for (int e = blockIdx.x; e < namb; e += gridDim.x) {
        if (threadIdx.x == 0) {
            int row = g_amb[e] >> 5;
            int slot = -1;
            if (atomicExch(&g_rowflag[row], 1) == 0) {
                int s = atomicAdd(&g_nrows, 1);
                if (s < FIX_ROWS) { g_rowlist[s] = row; slot = s; }
            }
            s_row = row; s_slot = slot;
        }
        __syncthreads();
        int slot = s_slot, row = s_row;
        if (slot >= 0) {
            bool f = first[row] != 0;
            for (int j = threadIdx.x; j < SDIM; j += blockDim.x)
                g_fin[(size_t)slot * 1088 + j] = f ? 0.f : stoch[(size_t)row * SDIM + j];
            for (int j = threadIdx.x; j < ADIM; j += blockDim.x)
                g_fin[(size_t)slot * 1088 + SDIM + j] = action[(size_t)row * ADIM + j];
            for (int j = threadIdx.x; j < REC; j += blockDim.x)
                g_fdet[(size_t)slot * 1024 + j] = f ? 0.f : deter[(size_t)row * REC + j];
            for (int j = threadIdx.x; j < HID; j += blockDim.x)
                g_fobs[(size_t)slot * 1024 + j] = obs[(size_t)row * HID + j];
        }
        __syncthreads();
    }
}

__global__ void fgru_kernel()
{
    int i = blockIdx.x * blockDim.x + threadIdx.x;
    if (i >= FIX_ROWS * 1024) return;
    int r = i >> 10, n = i & 1023;
    size_t base = (size_t)r * 3072 + n;
    float ir  = g_fgi[base];
    float iz  = g_fgi[base + 1024];
    float i_n = g_fgi[base + 2048];
    float hr  = g_fgh[base];
    float hz  = g_fgh[base + 1024];
    float h_n = g_fgh[base + 2048];
    float d = g_fdet[i];
    float rr = 1.f / (1.f + expf(-(ir + hr)));
    float zz = 1.f / (1.f + expf(-(iz + hz)));
    float nn = tanhf(i_n + rr * h_n);
    g_fh[i] = (1.f - zz) * nn + zz * d;
}

__global__ void fix_sample(float* __restrict__ stoch_out)
{
    int idx = blockIdx.x * blockDim.x + threadIdx.x;
    int r = idx >> 5, gl = idx & 31;
    if (r >= min(g_nrows, FIX_ROWS)) return;
    int row = g_rowlist[r];
    const float* l = g_flog + (size_t)r * 1024 + gl * 32;
    uint32_t base = ((uint32_t)row * 32u + (uint32_t)gl) * 32u;
    float best = -3.4e38f;
    int bi = 0;
#pragma unroll
    for (int d = 0; d < 32; d++) {
        float s = l[d] + gumbel_at(base + (uint32_t)d);
        if (s > best) { best = s; bi = d; }
    }
    float* dst = stoch_out + (size_t)row * 1024 + gl * 32;
#pragma unroll
    for (int d = 0; d < 32; d++) dst[d] = (d == bi) ? 1.f : 0.f;
}

// ---------------- launch ----------------
extern "C" void kernel_launch(void* const* d_in, const int* in_sizes, int n_in,
                              void* d_out, int out_size)
{
    (void)in_sizes; (void)n_in; (void)out_size;
    const float* stoch  = (const float*)d_in[0];
    const float* deter  = (const float*)d_in[1];
    const float* action = (const float*)d_in[3];
    const float* obs    = (const float*)d_in[4];
    const unsigned char* first = (const unsigned char*)d_in[5];
    const float* W_in   = (const float*)d_in[6];
    const float* b_in   = (const float*)d_in[7];
    const float* W_ih   = (const float*)d_in[8];
    const float* b_ih   = (const float*)d_in[9];
    const float* W_hh   = (const float*)d_in[10];
    const float* b_hh   = (const float*)d_in[11];
    const float* W_post = (const float*)d_in[14];
    const float* b_post = (const float*)d_in[15];

    float* out        = (float*)d_out;
    float* h_out      = out;
    float* stoch_out  = out + (size_t)BSZ * LATD;
    float* logits_out = out + 2 * (size_t)BSZ * LATD;

    float *gip, *ghp, *wt, *wc, *bc, *zb;
    float *fin, *fdet, *fobs, *fx, *fgi, *fgh, *fh, *flog;
    __nv_bfloat16 *acth, *actl, *deth, *detl, *hoh, *hol;
    __nv_bfloat16 *wihh, *wihl, *wth, *wtl, *wch, *wcl, *whhh, *whhl, *wph, *wpl;
    cudaGetSymbolAddress((void**)&gip, g_gi);
    cudaGetSymbolAddress((void**)&ghp, g_gh);
    cudaGetSymbolAddress((void**)&wt,  g_wt);
    cudaGetSymbolAddress((void**)&wc,  g_wc);
    cudaGetSymbolAddress((void**)&bc,  g_bc);
    cudaGetSymbolAddress((void**)&zb,  g_zb);
    cudaGetSymbolAddress((void**)&acth, g_act_h); cudaGetSymbolAddress((void**)&actl, g_act_l);
    cudaGetSymbolAddress((void**)&deth, g_det_h); cudaGetSymbolAddress((void**)&detl, g_det_l);
    cudaGetSymbolAddress((void**)&hoh,  g_ho_h);  cudaGetSymbolAddress((void**)&hol,  g_ho_l);
    cudaGetSymbolAddress((void**)&wihh, g_wih_h); cudaGetSymbolAddress((void**)&wihl, g_wih_l);
    cudaGetSymbolAddress((void**)&wth,  g_wt_h);  cudaGetSymbolAddress((void**)&wtl,  g_wt_l);
    cudaGetSymbolAddress((void**)&wch,  g_wc_h);  cudaGetSymbolAddress((void**)&wcl,  g_wc_l);
    cudaGetSymbolAddress((void**)&whhh, g_whh_h); cudaGetSymbolAddress((void**)&whhl, g_whh_l);
    cudaGetSymbolAddress((void**)&wph,  g_wp_h);  cudaGetSymbolAddress((void**)&wpl,  g_wp_l);
    cudaGetSymbolAddress((void**)&fin,  g_fin);
    cudaGetSymbolAddress((void**)&fdet, g_fdet);
    cudaGetSymbolAddress((void**)&fobs, g_fobs);
    cudaGetSymbolAddress((void**)&fx,   g_fx);
    cudaGetSymbolAddress((void**)&fgi,  g_fgi);
    cudaGetSymbolAddress((void**)&fgh,  g_fgh);
    cudaGetSymbolAddress((void**)&fh,   g_fh);
    cudaGetSymbolAddress((void**)&flog, g_flog);

    cudaFuncSetAttribute(bfgemm, cudaFuncAttributeMaxDynamicSharedMemorySize, SMEM_CA);

    dim3 thr(MMA_THR);
    auto blks = [](size_t n) { return (unsigned)((n + 255) / 256); };

    init_fix<<<64, 256>>>();

    // ---- prep: W_comb = W_ih @ W_in ----
    transpose_win<<<dim3(1280 / 32, 1024 / 32), dim3(32, 8)>>>(W_in);
    bcomb_kernel<<<3072 / 8, 256>>>(W_ih, b_in, b_ih);
    split_kernel<<<blks((size_t)3072 * 1024 / 4), 256>>>(
        W_ih, 1024, nullptr, 1024, 0, nullptr, wihh, wihl, 3072);
    split_kernel<<<blks((size_t)1280 * 1024 / 4), 256>>>(
        wt, 1024, nullptr, 1024, 0, nullptr, wth, wtl, 1280);
    bfgemm<<<dim3(1280 / 256, 3072 / 128), thr, SMEM_CA>>>(
        wihh, wihl, wth, wtl, zb, wc, 1280, 1024);
    split_kernel<<<blks((size_t)3072 * 1088 / 4), 256>>>(
        wc, 1280, nullptr, 1088, 0, nullptr, wch, wcl, 3072);

    // ---- split activations + remaining weights ----
    split_kernel<<<blks((size_t)BSZ * 1088 / 4), 256>>>(
        stoch, 1024, action, 1024, 64, first, acth, actl, BSZ);
    split_kernel<<<blks((size_t)BSZ * 1024 / 4), 256>>>(
        deter, 1024, nullptr, 1024, 0, first, deth, detl, BSZ);
    split_kernel<<<blks((size_t)3072 * 1024 / 4), 256>>>(
        W_hh, 1024, nullptr, 1024, 0, nullptr, whhh, whhl, 3072);
    split_kernel<<<blks((size_t)1024 * 2048 / 4), 256>>>(
        W_post, 2048, nullptr, 2048, 0, nullptr, wph, wpl, 1024);

    // ---- main GEMMs ----
    bfgemm<<<dim3(3072 / 256, BSZ / 128), thr, SMEM_CA>>>(
        acth, actl, wch, wcl, bc, gip, 3072, 1088);
    bfgemm<<<dim3(3072 / 256, BSZ / 128), thr, SMEM_CA>>>(
        deth, detl, whhh, whhl, b_hh, ghp, 3072, 1024);
    gru_kernel<<<(BSZ * REC) / 256, 256>>>(deter, first, h_out);
    split_kernel<<<blks((size_t)BSZ * 2048 / 4), 256>>>(
        h_out, 1024, obs, 1024, 1024, nullptr, hoh, hol, BSZ);
    bfgemm<<<dim3(1024 / 256, BSZ / 128), thr, SMEM_CA>>>(
        hoh, hol, wph, wpl, b_post, logits_out, 1024, 2048);
    sample_kernel<<<(BSZ * 32) / 256, 256>>>(logits_out, stoch_out);

    // ---- fp32 fix path (exact weights) ----
    gather_rows<<<256, 256>>>(stoch, deter, action, obs, first);
    gemm_f32<<<dim3(HID / GBN, FIX_ROWS / GBM), dim3(256)>>>(
        fin, 1088, fin, 0, W_in, b_in, fx, HID);
    gemm_f32<<<dim3(3 * REC / GBN, FIX_ROWS / GBM), dim3(256)>>>(
        fx, 1024, fx, 0, W_ih, b_ih, fgi, 3 * REC);
    gemm_f32<<<dim3(3 * REC / GBN, FIX_ROWS / GBM), dim3(256)>>>(
        fdet, 1024, fdet, 0, W_hh, b_hh, fgh, 3 * REC);
    fgru_kernel<<<(FIX_ROWS * 1024) / 256, 256>>>();
    gemm_f32<<<dim3(LATD / GBN, FIX_ROWS / GBM), dim3(256)>>>(
        fh, 1024, fobs, 1024, W_post, b_post, flog, LATD);
    fix_sample<<<(FIX_ROWS * 32) / 256, 256>>>(stoch_out);
}

// round 15
// speedup vs baseline: 1.2414x; 1.0776x over previous
#include <cuda_runtime.h>
#include <cuda_bf16.h>
#include <cstdint>
#include <cstddef>

#define BSZ  16384
#define SDIM 1024
#define ADIM 64
#define HID  1024
#define REC  1024
#define LATD 1024

// f32 scratch
__device__ float g_gi[(size_t)BSZ * 3 * REC];
__device__ float g_gh[(size_t)BSZ * 3 * REC];
__device__ float g_wt[(size_t)1280 * 1024];
__device__ float g_wc[(size_t)3072 * 1280];
__device__ float g_bc[3072];
__device__ float g_zb[1280];

// bf16 pre-split operand arrays (hi/lo)
__device__ __nv_bfloat16 g_act_h[(size_t)BSZ * 1088], g_act_l[(size_t)BSZ * 1088];
__device__ __nv_bfloat16 g_det_h[(size_t)BSZ * 1024], g_det_l[(size_t)BSZ * 1024];
__device__ __nv_bfloat16 g_ho_h [(size_t)BSZ * 2048], g_ho_l [(size_t)BSZ * 2048];
__device__ __nv_bfloat16 g_wih_h[(size_t)3072 * 1024], g_wih_l[(size_t)3072 * 1024];
__device__ __nv_bfloat16 g_wt_h [(size_t)1280 * 1024], g_wt_l [(size_t)1280 * 1024];
__device__ __nv_bfloat16 g_wc_h [(size_t)3072 * 1088], g_wc_l [(size_t)3072 * 1088];
__device__ __nv_bfloat16 g_whh_h[(size_t)3072 * 1024], g_whh_l[(size_t)3072 * 1024];
__device__ __nv_bfloat16 g_wp_h [(size_t)1024 * 2048], g_wp_l [(size_t)1024 * 2048];

// ---- ambiguous-group fix machinery ----
#define FIX_TAU  2e-4f
#define AMB_CAP  16384
#define FIX_ROWS 512
__device__ int   g_namb;
__device__ int   g_nrows;
__device__ int   g_amb[AMB_CAP];
__device__ int   g_rowlist[FIX_ROWS];
__device__ int   g_rowflag[BSZ];
__device__ float g_fin [(size_t)FIX_ROWS * 1088];
__device__ float g_fdet[(size_t)FIX_ROWS * 1024];
__device__ float g_fobs[(size_t)FIX_ROWS * 1024];
__device__ float g_fx  [(size_t)FIX_ROWS * 1024];
__device__ float g_fgi [(size_t)FIX_ROWS * 3072];
__device__ float g_fgh [(size_t)FIX_ROWS * 3072];
__device__ float g_fh  [(size_t)FIX_ROWS * 1024];
__device__ float g_flog[(size_t)FIX_ROWS * 1024];

__device__ __forceinline__ uint32_t smem_u32(const void* p) {
    uint32_t a;
    asm("{ .reg .u64 t; cvta.to.shared.u64 t, %1; cvt.u32.u64 %0, t; }"
        : "=r"(a) : "l"(p));
    return a;
}
__device__ __forceinline__ void splitbf(float x0, float x1, uint32_t& hi, uint32_t& lo) {
    uint32_t u0 = __float_as_uint(x0), u1 = __float_as_uint(x1);
    uint32_t h;
    asm("prmt.b32 %0, %1, %2, 0x7632;" : "=r"(h) : "r"(u0), "r"(u1));
    hi = h;
    float f0 = __uint_as_float(u0 & 0xFFFF0000u);
    float f1 = __uint_as_float(u1 & 0xFFFF0000u);
    float r0 = x0 - f0;
    float r1 = x1 - f1;
    asm("cvt.rn.bf16x2.f32 %0, %1, %2;" : "=r"(lo) : "f"(r1), "f"(r0));
}

// ---------------- generic split kernel ----------------
__global__ void split_kernel(const float* __restrict__ src, int srcStride,
                             const float* __restrict__ src2, int K1, int K2,
                             const unsigned char* __restrict__ mask,
                             __nv_bfloat16* __restrict__ hi,
                             __nv_bfloat16* __restrict__ lo,
                             int rows)
{
    const int Kd = K1 + K2;
    size_t e = ((size_t)blockIdx.x * blockDim.x + threadIdx.x) * 4;
    if (e >= (size_t)rows * Kd) return;
    int r = (int)(e / Kd);
    int j = (int)(e % Kd);
    float4 v;
    if (j < K1) {
        if (mask != nullptr && mask[r]) v = make_float4(0.f, 0.f, 0.f, 0.f);
        else v = *reinterpret_cast<const float4*>(src + (size_t)r * srcStride + j);
    } else {
        v = *reinterpret_cast<const float4*>(src2 + (size_t)r * K2 + (j - K1));
    }
    uint32_t h0, h1, l0, l1;
    splitbf(v.x, v.y, h0, l0);
    splitbf(v.z, v.w, h1, l1);
    size_t d = (size_t)r * Kd + j;
    *reinterpret_cast<uint2*>(hi + d) = make_uint2(h0, h1);
    *reinterpret_cast<uint2*>(lo + d) = make_uint2(l0, l1);
}

// ---------------- prep kernels ----------------
__global__ void transpose_win(const float* __restrict__ W_in)
{
    __shared__ float tile[32][33];
    int j0 = blockIdx.x << 5, h0 = blockIdx.y << 5;
    int tx = threadIdx.x, ty = threadIdx.y;
#pragma unroll
    for (int i = 0; i < 4; i++) {
        int h = h0 + ty + i * 8, j = j0 + tx;
        tile[ty + i * 8][tx] = (j < SDIM + ADIM) ? W_in[(size_t)h * (SDIM + ADIM) + j] : 0.f;
    }
    __syncthreads();
#pragma unroll
    for (int i = 0; i < 4; i++) {
        int j = j0 + ty + i * 8, h = h0 + tx;
        g_wt[(size_t)j * 1024 + h] = tile[tx][ty + i * 8];
    }
}

__global__ void bcomb_kernel(const float* __restrict__ W_ih,
                             const float* __restrict__ b_in,
                             const float* __restrict__ b_ih)
{
    int n = blockIdx.x * (blockDim.x >> 5) + (threadIdx.x >> 5);
    if (n >= 3072) return;
    int lane = threadIdx.x & 31;
    float s = 0.f;
    const float* row = W_ih + (size_t)n * 1024;
    for (int h = lane; h < 1024; h += 32) s += row[h] * b_in[h];
#pragma unroll
    for (int o = 16; o; o >>= 1) s += __shfl_xor_sync(0xFFFFFFFFu, s, o);
    if (lane == 0) g_bc[n] = s + b_ih[n];
}

// ---------------- bf16 hi/lo GEMM, K-chunk 64, 2-stage, dual operand sets ----
#define MMA_THR 512
#define HALF_BYTES 49152                      // Ah 8K | Al 8K | Bh 16K | Bl 16K
#define STG_BYTES  (2 * HALF_BYTES)           // 98304 per chunk64 stage
#define SMEM_CA    (2 * STG_BYTES)            // 196608
#define OFFB_AH 0
#define OFFB_AL 8192
#define OFFB_BH 16384
#define OFFB_BL 32768

struct GemmArgs {
    const __nv_bfloat16 *Ah, *Al, *Bh, *Bl;
    const float* bias;
    float* C;
    int Ntot, K;
};

__device__ __forceinline__ void mma16(float c[4], const uint32_t a[4], const uint32_t b[2]) {
    asm volatile("mma.sync.aligned.m16n8k16.row.col.f32.bf16.bf16.f32 "
                 "{%0,%1,%2,%3}, {%4,%5,%6,%7}, {%8,%9}, {%0,%1,%2,%3};"
                 : "+f"(c[0]), "+f"(c[1]), "+f"(c[2]), "+f"(c[3])
                 : "r"(a[0]), "r"(a[1]), "r"(a[2]), "r"(a[3]), "r"(b[0]), "r"(b[1]));
}
__device__ __forceinline__ void cp16(uint32_t dst, const void* src) {
    asm volatile("cp.async.cg.shared.global [%0], [%1], 16;"
                 :: "r"(dst), "l"(src) : "memory");
}
#define CP_COMMIT() asm volatile("cp.async.commit_group;" ::: "memory")
#define CP_WAIT0()  asm volatile("cp.async.wait_group 0;" ::: "memory")

__global__ __launch_bounds__(MMA_THR, 1)
void bfgemm(GemmArgs arg0, GemmArgs arg1)
{
    extern __shared__ __align__(16) char smc[];
    const uint32_t sbase = smem_u32(smc);
    const uint32_t* smw = reinterpret_cast<const uint32_t*>(smc);

    const GemmArgs& A = blockIdx.z ? arg1 : arg0;
    const __nv_bfloat16* __restrict__ Ah = A.Ah;
    const __nv_bfloat16* __restrict__ Al = A.Al;
    const __nv_bfloat16* __restrict__ Bh = A.Bh;
    const __nv_bfloat16* __restrict__ Bl = A.Bl;
    const int K = A.K;
    const int KC = K >> 6;

    const int bm = blockIdx.y << 7;
    const int bn = blockIdx.x << 8;
    const int t  = threadIdx.x;
    const int wid  = t >> 5;
    const int lane = t & 31;
    const int g = lane >> 2;
    const int c = lane & 3;
    const int wm = (wid >> 2) << 5;
    const int wn = (wid & 3) << 6;

    const int rowA = t >> 2;
    const int qA   = t & 3;
    const uint32_t dA = (uint32_t)(rowA * 64 + ((qA ^ ((rowA >> 1) & 3)) << 4));
    const int rB0 = t >> 2, rB1 = (t + 512) >> 2;
    const uint32_t dB0 = (uint32_t)(rB0 * 64 + ((qA ^ ((rB0 >> 1) & 3)) << 4));
    const uint32_t dB1 = (uint32_t)(rB1 * 64 + ((qA ^ ((rB1 >> 1) & 3)) << 4));

    auto issue_stage = [&](int kc) {
        if (kc < KC) {
            const uint32_t st = sbase + (uint32_t)(kc & 1) * STG_BYTES;
#pragma unroll
            for (int h = 0; h < 2; h++) {
                const uint32_t hb = st + (uint32_t)h * HALF_BYTES;
                const int ke = (kc << 6) + (h << 5) + (qA << 3);
                cp16(hb + OFFB_AH + dA, Ah + (size_t)(bm + rowA) * K + ke);
                cp16(hb + OFFB_AL + dA, Al + (size_t)(bm + rowA) * K + ke);
                cp16(hb + OFFB_BH + dB0, Bh + (size_t)(bn + rB0) * K + ke);
                cp16(hb + OFFB_BH + dB1, Bh + (size_t)(bn + rB1) * K + ke);
                cp16(hb + OFFB_BL + dB0, Bl + (size_t)(bn + rB0) * K + ke);
                cp16(hb + OFFB_BL + dB1, Bl + (size_t)(bn + rB1) * K + ke);
            }
        }
        CP_COMMIT();
    };

    float acc[2][8][4];
#pragma unroll
    for (int i = 0; i < 2; i++)
#pragma unroll
        for (int j = 0; j < 8; j++)
#pragma unroll
            for (int r = 0; r < 4; r++) acc[i][j][r] = 0.f;

    issue_stage(0);

    const int swzf = ((g >> 1) & 3) << 2;

    for (int k = 0; k < KC; k++) {
        CP_WAIT0();               // copy k fully landed
        __syncthreads();          // all warps done reading the other buffer
        issue_stage(k + 1);       // overlaps compute(k)

        const uint32_t stg = (uint32_t)(k & 1) * (STG_BYTES / 4);
#pragma unroll
        for (int h = 0; h < 2; h++) {
            const uint32_t* S  = smw + stg + (uint32_t)h * (HALF_BYTES / 4);
            const uint32_t* AH = S;
            const uint32_t* AL = S + OFFB_AL / 4;
            const uint32_t* BH = S + OFFB_BH / 4;
            const uint32_t* BL = S + OFFB_BL / 4;
#pragma unroll
            for (int ks = 0; ks < 2; ks++) {
                const int w0 = ((ks << 3) + c) ^ swzf;
                const int w1 = ((ks << 3) + 4 + c) ^ swzf;
                uint32_t aH[2][4], aL[2][4];
#pragma unroll
                for (int i = 0; i < 2; i++) {
                    int r0 = (wm + (i << 4) + g) << 4;
                    int r1 = r0 + (8 << 4);
                    aH[i][0] = AH[r0 + w0]; aH[i][1] = AH[r1 + w0];
                    aH[i][2] = AH[r0 + w1]; aH[i][3] = AH[r1 + w1];
                    aL[i][0] = AL[r0 + w0]; aL[i][1] = AL[r1 + w0];
                    aL[i][2] = AL[r0 + w1]; aL[i][3] = AL[r1 + w1];
                }
#pragma unroll
                for (int jp = 0; jp < 4; jp++) {
                    uint32_t bH[2][2], bL[2][2];
#pragma unroll
                    for (int q = 0; q < 2; q++) {
                        int j = jp * 2 + q;
                        int r0 = (wn + (j << 3) + g) << 4;
                        bH[q][0] = BH[r0 + w0]; bH[q][1] = BH[r0 + w1];
                        bL[q][0] = BL[r0 + w0]; bL[q][1] = BL[r0 + w1];
                    }
#pragma unroll
                    for (int i = 0; i < 2; i++)
#pragma unroll
                        for (int q = 0; q < 2; q++) {
                            mma16(acc[i][jp * 2 + q], aH[i], bH[q]);
                            mma16(acc[i][jp * 2 + q], aL[i], bH[q]);
                            mma16(acc[i][jp * 2 + q], aH[i], bL[q]);
                        }
                }
            }
        }
    }

    const float* bias = A.bias;
    float* C = A.C;
    const int Ntot = A.Ntot;
#pragma unroll
    for (int i = 0; i < 2; i++) {
        int row0 = bm + wm + (i << 4) + g;
        int row1 = row0 + 8;
#pragma unroll
        for (int j = 0; j < 8; j++) {
            int col = bn + wn + (j << 3) + (c << 1);
            float2 b2 = *reinterpret_cast<const float2*>(bias + col);
            float2 v0 = make_float2(acc[i][j][0] + b2.x, acc[i][j][1] + b2.y);
            float2 v1 = make_float2(acc[i][j][2] + b2.x, acc[i][j][3] + b2.y);
            *reinterpret_cast<float2*>(C + (size_t)row0 * Ntot + col) = v0;
            *reinterpret_cast<float2*>(C + (size_t)row1 * Ntot + col) = v1;
        }
    }
}

// ---------------- fp32 FFMA GEMM (fix path) ----------------
#define GBM 128
#define GBN 128
#define GBK 16
#define GTM 8
#define GTN 8

__global__ __launch_bounds__(256, 2)
void gemm_f32(const float* __restrict__ A1, int K1,
              const float* __restrict__ A2, int K2,
              const float* __restrict__ B,
              const float* __restrict__ bias,
              float* __restrict__ C, int N)
{
    __shared__ __align__(16) float As[GBK][GBM];
    __shared__ __align__(16) float Bs[GBK][GBN];
    const int K  = K1 + K2;
    const int bm = blockIdx.y * GBM;
    const int bn = blockIdx.x * GBN;
    const int t  = threadIdx.x;
    const int tx = t & 15;
    const int ty = t >> 4;

    float acc[GTM][GTN];
#pragma unroll
    for (int i = 0; i < GTM; i++)
#pragma unroll
        for (int j = 0; j < GTN; j++) acc[i][j] = 0.f;

    for (int kt = 0; kt < K; kt += GBK) {
#pragma unroll
        for (int q = 0; q < 2; q++) {
            int li  = t * 2 + q;
            int row = li >> 2;
            int kq  = (li & 3) << 2;
            int kg  = kt + kq;
            {
                int m = bm + row;
                float4 v;
                if (kg < K1) v = *reinterpret_cast<const float4*>(A1 + (size_t)m * K1 + kg);
                else         v = *reinterpret_cast<const float4*>(A2 + (size_t)m * K2 + (kg - K1));
                As[kq + 0][row] = v.x; As[kq + 1][row] = v.y;
                As[kq + 2][row] = v.z; As[kq + 3][row] = v.w;
            }
            {
                int n = bn + row;
                float4 w = *reinterpret_cast<const float4*>(B + (size_t)n * K + kg);
                Bs[kq + 0][row] = w.x; Bs[kq + 1][row] = w.y;
                Bs[kq + 2][row] = w.z; Bs[kq + 3][row] = w.w;
            }
        }
        __syncthreads();
#pragma unroll
        for (int k = 0; k < GBK; k++) {
            float4 a0 = *reinterpret_cast<const float4*>(&As[k][ty * GTM]);
            float4 a1 = *reinterpret_cast<const float4*>(&As[k][ty * GTM + 4]);
            float4 b0 = *reinterpret_cast<const float4*>(&Bs[k][tx * GTN]);
            float4 b1 = *reinterpret_cast<const float4*>(&Bs[k][tx * GTN + 4]);
            float a[8] = {a0.x, a0.y, a0.z, a0.w, a1.x, a1.y, a1.z, a1.w};
            float b[8] = {b0.x, b0.y, b0.z, b0.w, b1.x, b1.y, b1.z, b1.w};
#pragma unroll
            for (int i = 0; i < GTM; i++)
#pragma unroll
                for (int j = 0; j < GTN; j++)
                    acc[i][j] = fmaf(a[i], b[j], acc[i][j]);
        }
        __syncthreads();
    }
#pragma unroll
    for (int i = 0; i < GTM; i++) {
        int m = bm + ty * GTM + i;
        float* crow = C + (size_t)m * N + bn + tx * GTN;
#pragma unroll
        for (int j = 0; j < GTN; j++)
            crow[j] = acc[i][j] + bias[bn + tx * GTN + j];
    }
}

// ---------------- GRU elementwise combine ----------------
__global__ void gru_kernel(const float* __restrict__ deter,
                           const unsigned char* __restrict__ first,
                           float* __restrict__ h_out)
{
    int i = blockIdx.x * blockDim.x + threadIdx.x;
    if (i >= BSZ * REC) return;
    int m = i >> 10;
    int n = i & 1023;
    size_t base = (size_t)m * (3 * REC) + n;
    float ir  = g_gi[base];
    float iz  = g_gi[base + REC];
    float i_n = g_gi[base + 2 * REC];
    float hr  = g_gh[base];
    float hz  = g_gh[base + REC];
    float h_n = g_gh[base + 2 * REC];
    float d = first[m] ? 0.f : deter[i];
    float r  = 1.f / (1.f + expf(-(ir + hr)));
    float z  = 1.f / (1.f + expf(-(iz + hz)));
    float nn = tanhf(i_n + r * h_n);
    h_out[i] = (1.f - z) * nn + z * d;
}

// ---------------- threefry2x32 + gumbel ----------------
__device__ __forceinline__ uint32_t threefry_bits(uint32_t x1in)
{
    const uint32_t ks0 = 0u;
    const uint32_t ks1 = 42u;
    const uint32_t ks2 = 0x1BD11BDAu ^ ks0 ^ ks1;
    uint32_t x0 = 0u + ks0;
    uint32_t x1 = x1in + ks1;
#define TF_R(r) { x0 += x1; x1 = __funnelshift_l(x1, x1, (r)); x1 ^= x0; }
    TF_R(13) TF_R(15) TF_R(26) TF_R(6)
    x0 += ks1; x1 += ks2 + 1u;
    TF_R(17) TF_R(29) TF_R(16) TF_R(24)
    x0 += ks2; x1 += ks0 + 2u;
    TF_R(13) TF_R(15) TF_R(26) TF_R(6)
    x0 += ks0; x1 += ks1 + 3u;
    TF_R(17) TF_R(29) TF_R(16) TF_R(24)
    x0 += ks1; x1 += ks2 + 4u;
    TF_R(13) TF_R(15) TF_R(26) TF_R(6)
    x0 += ks2; x1 += ks0 + 5u;
#undef TF_R
    return x0 ^ x1;
}

__device__ __forceinline__ float gumbel_at(uint32_t idx)
{
    uint32_t bits = threefry_bits(idx);
    float f = __uint_as_float((bits >> 9) | 0x3f800000u) - 1.0f;
    float u = fmaxf(f, 1.17549435e-38f);
    float inner = -logf(u);
    return -__logf(inner);
}

__global__ void sample_kernel(const float* __restrict__ logits,
                              float* __restrict__ stoch_out)
{
    int g = blockIdx.x * blockDim.x + threadIdx.x;
    if (g >= BSZ * 32) return;
    const float4* lrow = reinterpret_cast<const float4*>(logits + (size_t)g * 32);
    float best = -3.4e38f, second = -3.4e38f;
    int   bi   = 0;
    uint32_t base = (uint32_t)g * 32u;
#pragma unroll
    for (int q = 0; q < 8; q++) {
        float4 lv = lrow[q];
        float l4[4] = {lv.x, lv.y, lv.z, lv.w};
#pragma unroll
        for (int ci = 0; ci < 4; ci++) {
            int d = q * 4 + ci;
            float s = l4[ci] + gumbel_at(base + (uint32_t)d);
            if (s > best) { second = best; best = s; bi = d; }
            else if (s > second) second = s;
        }
    }
    float4* dst = reinterpret_cast<float4*>(stoch_out + (size_t)g * 32);
#pragma unroll
    for (int q = 0; q < 8; q++) {
        float4 v;
        v.x = (bi == q * 4 + 0) ? 1.f : 0.f;
        v.y = (bi == q * 4 + 1) ? 1.f : 0.f;
        v.z = (bi == q * 4 + 2) ? 1.f : 0.f;
        v.w = (bi == q * 4 + 3) ? 1.f : 0.f;
        dst[q] = v;
    }
    if (best - second < FIX_TAU) {
        int slot = atomicAdd(&g_namb, 1);
        if (slot < AMB_CAP) g_amb[slot] = g;
    }
}

// ---------------- fix path ----------------
__global__ void init_fix()
{
    int t = blockIdx.x * blockDim.x + threadIdx.x;
    if (t == 0) { g_namb = 0; g_nrows = 0; }
    for (int i = t; i < BSZ; i += gridDim.x * blockDim.x) g_rowflag[i] = 0;
}

__global__ void gather_rows(const float* __restrict__ stoch,
                            const float* __restrict__ deter,
                            const float* __restrict__ action,
                            const float* __restrict__ obs,
                            const unsigned char* __restrict__ first)
{
    __shared__ int s_row, s_slot;
    int namb = min(g_namb, AMB_CAP);
    for (int e = blockIdx.x; e < namb; e += gridDim.x) {
        if (threadIdx.x == 0) {
            int row = g_amb[e] >> 5;
            int slot = -1;
            if (atomicExch(&g_rowflag[row], 1) == 0) {
                int s = atomicAdd(&g_nrows, 1);
                if (s < FIX_ROWS) { g_rowlist[s] = row; slot = s; }
            }
            s_row = row; s_slot = slot;
        }
        __syncthreads();
        int slot = s_slot, row = s_row;
        if (slot >= 0) {
            bool f = first[row] != 0;
            for (int j = threadIdx.x; j < SDIM; j += blockDim.x)
                g_fin[(size_t)slot * 1088 + j] = f ? 0.f : stoch[(size_t)row * SDIM + j];
            for (int j = threadIdx.x; j < ADIM; j += blockDim.x)
                g_fin[(size_t)slot * 1088 + SDIM + j] = action[(size_t)row * ADIM + j];
            for (int j = threadIdx.x; j < REC; j += blockDim.x)
                g_fdet[(size_t)slot * 1024 + j] = f ? 0.f : deter[(size_t)row * REC + j];
            for (int j = threadIdx.x; j < HID; j += blockDim.x)
                g_fobs[(size_t)slot * 1024 + j] = obs[(size_t)row * HID + j];
        }
        __syncthreads();
    }
}

__global__ void fgru_kernel()
{
    int i = blockIdx.x * blockDim.x + threadIdx.x;
    if (i >= FIX_ROWS * 1024) return;
    int r = i >> 10, n = i & 1023;
    size_t base = (size_t)r * 3072 + n;
    float ir  = g_fgi[base];
    float iz  = g_fgi[base + 1024];
    float i_n = g_fgi[base + 2048];
    float hr  = g_fgh[base];
    float hz  = g_fgh[base + 1024];
    float h_n = g_fgh[base + 2048];
    float d = g_fdet[i];
    float rr = 1.f / (1.f + expf(-(ir + hr)));
    float zz = 1.f / (1.f + expf(-(iz + hz)));
    float nn = tanhf(i_n + rr * h_n);
    g_fh[i] = (1.f - zz) * nn + zz * d;
}

__global__ void fix_sample(float* __restrict__ stoch_out)
{
    int idx = blockIdx.x * blockDim.x + threadIdx.x;
    int r = idx >> 5, gl = idx & 31;
    if (r >= min(g_nrows, FIX_ROWS)) return;
    int row = g_rowlist[r];
    const float* l = g_flog + (size_t)r * 1024 + gl * 32;
    uint32_t base = ((uint32_t)row * 32u + (uint32_t)gl) * 32u;
    float best = -3.4e38f;
    int bi = 0;
#pragma unroll
    for (int d = 0; d < 32; d++) {
        float s = l[d] + gumbel_at(base + (uint32_t)d);
        if (s > best) { best = s; bi = d; }
    }
    float* dst = stoch_out + (size_t)row * 1024 + gl * 32;
#pragma unroll
    for (int d = 0; d < 32; d++) dst[d] = (d == bi) ? 1.f : 0.f;
}

// ---------------- launch ----------------
extern "C" void kernel_launch(void* const* d_in, const int* in_sizes, int n_in,
                              void* d_out, int out_size)
{
    (void)in_sizes; (void)n_in; (void)out_size;
    const float* stoch  = (const float*)d_in[0];
    const float* deter  = (const float*)d_in[1];
    const float* action = (const float*)d_in[3];
    const float* obs    = (const float*)d_in[4];
    const unsigned char* first = (const unsigned char*)d_in[5];
    const float* W_in   = (const float*)d_in[6];
    const float* b_in   = (const float*)d_in[7];
    const float* W_ih   = (const float*)d_in[8];
    const float* b_ih   = (const float*)d_in[9];
    const float* W_hh   = (const float*)d_in[10];
    const float* b_hh   = (const float*)d_in[11];
    const float* W_post = (const float*)d_in[14];
    const float* b_post = (const float*)d_in[15];

    float* out        = (float*)d_out;
    float* h_out      = out;
    float* stoch_out  = out + (size_t)BSZ * LATD;
    float* logits_out = out + 2 * (size_t)BSZ * LATD;

    float *gip, *ghp, *wt, *wc, *bc, *zb;
    float *fin, *fdet, *fobs, *fx, *fgi, *fgh, *fh, *flog;
    __nv_bfloat16 *acth, *actl, *deth, *detl, *hoh, *hol;
    __nv_bfloat16 *wihh, *wihl, *wth, *wtl, *wch, *wcl, *whhh, *whhl, *wph, *wpl;
    cudaGetSymbolAddress((void**)&gip, g_gi);
    cudaGetSymbolAddress((void**)&ghp, g_gh);
    cudaGetSymbolAddress((void**)&wt,  g_wt);
    cudaGetSymbolAddress((void**)&wc,  g_wc);
    cudaGetSymbolAddress((void**)&bc,  g_bc);
    cudaGetSymbolAddress((void**)&zb,  g_zb);
    cudaGetSymbolAddress((void**)&acth, g_act_h); cudaGetSymbolAddress((void**)&actl, g_act_l);
    cudaGetSymbolAddress((void**)&deth, g_det_h); cudaGetSymbolAddress((void**)&detl, g_det_l);
    cudaGetSymbolAddress((void**)&hoh,  g_ho_h);  cudaGetSymbolAddress((void**)&hol,  g_ho_l);
    cudaGetSymbolAddress((void**)&wihh, g_wih_h); cudaGetSymbolAddress((void**)&wihl, g_wih_l);
    cudaGetSymbolAddress((void**)&wth,  g_wt_h);  cudaGetSymbolAddress((void**)&wtl,  g_wt_l);
    cudaGetSymbolAddress((void**)&wch,  g_wc_h);  cudaGetSymbolAddress((void**)&wcl,  g_wc_l);
    cudaGetSymbolAddress((void**)&whhh, g_whh_h); cudaGetSymbolAddress((void**)&whhl, g_whh_l);
    cudaGetSymbolAddress((void**)&wph,  g_wp_h);  cudaGetSymbolAddress((void**)&wpl,  g_wp_l);
    cudaGetSymbolAddress((void**)&fin,  g_fin);
    cudaGetSymbolAddress((void**)&fdet, g_fdet);
    cudaGetSymbolAddress((void**)&fobs, g_fobs);
    cudaGetSymbolAddress((void**)&fx,   g_fx);
    cudaGetSymbolAddress((void**)&fgi,  g_fgi);
    cudaGetSymbolAddress((void**)&fgh,  g_fgh);
    cudaGetSymbolAddress((void**)&fh,   g_fh);
    cudaGetSymbolAddress((void**)&flog, g_flog);

    cudaFuncSetAttribute(bfgemm, cudaFuncAttributeMaxDynamicSharedMemorySize, SMEM_CA);

    dim3 thr(MMA_THR);
    auto blks = [](size_t n) { return (unsigned)((n + 255) / 256); };

    init_fix<<<64, 256>>>();

    // ---- prep: W_comb = W_ih @ W_in ----
    transpose_win<<<dim3(1280 / 32, 1024 / 32), dim3(32, 8)>>>(W_in);
    bcomb_kernel<<<3072 / 8, 256>>>(W_ih, b_in, b_ih);
    split_kernel<<<blks((size_t)3072 * 1024 / 4), 256>>>(
        W_ih, 1024, nullptr, 1024, 0, nullptr, wihh, wihl, 3072);
    split_kernel<<<blks((size_t)1280 * 1024 / 4), 256>>>(
        wt, 1024, nullptr, 1024, 0, nullptr, wth, wtl, 1280);
    {
        GemmArgs a{wihh, wihl, wth, wtl, zb, wc, 1280, 1024};
        bfgemm<<<dim3(1280 / 256, 3072 / 128, 1), thr, SMEM_CA>>>(a, a);
    }
    split_kernel<<<blks((size_t)3072 * 1088 / 4), 256>>>(
        wc, 1280, nullptr, 1088, 0, nullptr, wch, wcl, 3072);

    // ---- split activations + remaining weights ----
    split_kernel<<<blks((size_t)BSZ * 1088 / 4), 256>>>(
        stoch, 1024, action, 1024, 64, first, acth, actl, BSZ);
    split_kernel<<<blks((size_t)BSZ * 1024 / 4), 256>>>(
        deter, 1024, nullptr, 1024, 0, first, deth, detl, BSZ);
    split_kernel<<<blks((size_t)3072 * 1024 / 4), 256>>>(
        W_hh, 1024, nullptr, 1024, 0, nullptr, whhh, whhl, 3072);
    split_kernel<<<blks((size_t)1024 * 2048 / 4), 256>>>(
        W_post, 2048, nullptr, 2048, 0, nullptr, wph, wpl, 1024);

    // ---- main GEMMs: gi and gh merged into one launch (z selects) ----
    {
        GemmArgs agi{acth, actl, wch, wcl, bc, gip, 3072, 1088};
        GemmArgs agh{deth, detl, whhh, whhl, b_hh, ghp, 3072, 1024};
        bfgemm<<<dim3(3072 / 256, BSZ / 128, 2), thr, SMEM_CA>>>(agi, agh);
    }
    gru_kernel<<<(BSZ * REC) / 256, 256>>>(deter, first, h_out);
    split_kernel<<<blks((size_t)BSZ * 2048 / 4), 256>>>(
        h_out, 1024, obs, 1024, 1024, nullptr, hoh, hol, BSZ);
    {
        GemmArgs alg{hoh, hol, wph, wpl, b_post, logits_out, 1024, 2048};
        bfgemm<<<dim3(1024 / 256, BSZ / 128, 1), thr, SMEM_CA>>>(alg, alg);
    }
    sample_kernel<<<(BSZ * 32) / 256, 256>>>(logits_out, stoch_out);

    // ---- fp32 fix path (exact weights) ----
    gather_rows<<<256, 256>>>(stoch, deter, action, obs, first);
    gemm_f32<<<dim3(HID / GBN, FIX_ROWS / GBM), dim3(256)>>>(
        fin, 1088, fin, 0, W_in, b_in, fx, HID);
    gemm_f32<<<dim3(3 * REC / GBN, FIX_ROWS / GBM), dim3(256)>>>(
        fx, 1024, fx, 0, W_ih, b_ih, fgi, 3 * REC);
    gemm_f32<<<dim3(3 * REC / GBN, FIX_ROWS / GBM), dim3(256)>>>(
        fdet, 1024, fdet, 0, W_hh, b_hh, fgh, 3 * REC);
    fgru_kernel<<<(FIX_ROWS * 1024) / 256, 256>>>();
    gemm_f32<<<dim3(LATD / GBN, FIX_ROWS / GBM), dim3(256)>>>(
        fh, 1024, fobs, 1024, W_post, b_post, flog, LATD);
    fix_sample<<<(FIX_ROWS * 32) / 256, 256>>>(stoch_out);
}

// round 16
// speedup vs baseline: 1.4078x; 1.1341x over previous
#include <cuda_runtime.h>
#include <cuda_bf16.h>
#include <cstdint>
#include <cstddef>

#define BSZ  16384
#define SDIM 1024
#define ADIM 64
#define HID  1024
#define REC  1024
#define LATD 1024

// f32 scratch
__device__ float g_gi[(size_t)BSZ * 3 * REC];
__device__ float g_gh[(size_t)BSZ * 3 * REC];
__device__ float g_wt[(size_t)1280 * 1024];
__device__ float g_wc[(size_t)3072 * 1280];
__device__ float g_bc[3072];
__device__ float g_zb[1280];

// bf16 pre-split operand arrays (hi/lo)
__device__ __nv_bfloat16 g_act_h[(size_t)BSZ * 1088], g_act_l[(size_t)BSZ * 1088];
__device__ __nv_bfloat16 g_det_h[(size_t)BSZ * 1024], g_det_l[(size_t)BSZ * 1024];
__device__ __nv_bfloat16 g_ho_h [(size_t)BSZ * 2048], g_ho_l [(size_t)BSZ * 2048];
__device__ __nv_bfloat16 g_wih_h[(size_t)3072 * 1024], g_wih_l[(size_t)3072 * 1024];
__device__ __nv_bfloat16 g_wt_h [(size_t)1280 * 1024], g_wt_l [(size_t)1280 * 1024];
__device__ __nv_bfloat16 g_wc_h [(size_t)3072 * 1088], g_wc_l [(size_t)3072 * 1088];
__device__ __nv_bfloat16 g_whh_h[(size_t)3072 * 1024], g_whh_l[(size_t)3072 * 1024];
__device__ __nv_bfloat16 g_wp_h [(size_t)1024 * 2048], g_wp_l [(size_t)1024 * 2048];

// ---- ambiguous-group fix machinery ----
#define FIX_TAU  1e-4f
#define AMB_CAP  16384
#define FIX_ROWS 256
__device__ int   g_namb;
__device__ int   g_nrows;
__device__ int   g_amb[AMB_CAP];
__device__ int   g_rowlist[FIX_ROWS];
__device__ int   g_rowflag[BSZ];
__device__ float g_fin [(size_t)FIX_ROWS * 1088];
__device__ float g_fdet[(size_t)FIX_ROWS * 1024];
__device__ float g_fobs[(size_t)FIX_ROWS * 1024];
__device__ float g_fx  [(size_t)FIX_ROWS * 1024];
__device__ float g_fgi [(size_t)FIX_ROWS * 3072];
__device__ float g_fgh [(size_t)FIX_ROWS * 3072];
__device__ float g_fh  [(size_t)FIX_ROWS * 1024];
__device__ float g_flog[(size_t)FIX_ROWS * 1024];

__device__ __forceinline__ uint32_t smem_u32(const void* p) {
    uint32_t a;
    asm("{ .reg .u64 t; cvta.to.shared.u64 t, %1; cvt.u32.u64 %0, t; }"
        : "=r"(a) : "l"(p));
    return a;
}
__device__ __forceinline__ void splitbf(float x0, float x1, uint32_t& hi, uint32_t& lo) {
    uint32_t u0 = __float_as_uint(x0), u1 = __float_as_uint(x1);
    uint32_t h;
    asm("prmt.b32 %0, %1, %2, 0x7632;" : "=r"(h) : "r"(u0), "r"(u1));
    hi = h;
    float f0 = __uint_as_float(u0 & 0xFFFF0000u);
    float f1 = __uint_as_float(u1 & 0xFFFF0000u);
    float r0 = x0 - f0;
    float r1 = x1 - f1;
    asm("cvt.rn.bf16x2.f32 %0, %1, %2;" : "=r"(lo) : "f"(r1), "f"(r0));
}

// ---------------- generic split kernel (strided dst) ----------------
__global__ void split_kernel(const float* __restrict__ src, int srcStride,
                             const float* __restrict__ src2, int K1, int K2,
                             const unsigned char* __restrict__ mask,
                             __nv_bfloat16* __restrict__ hi,
                             __nv_bfloat16* __restrict__ lo,
                             int rows, int dstStride)
{
    const int Kd = K1 + K2;
    size_t e = ((size_t)blockIdx.x * blockDim.x + threadIdx.x) * 4;
    if (e >= (size_t)rows * Kd) return;
    int r = (int)(e / Kd);
    int j = (int)(e % Kd);
    float4 v;
    if (j < K1) {
        if (mask != nullptr && mask[r]) v = make_float4(0.f, 0.f, 0.f, 0.f);
        else v = *reinterpret_cast<const float4*>(src + (size_t)r * srcStride + j);
    } else {
        v = *reinterpret_cast<const float4*>(src2 + (size_t)r * K2 + (j - K1));
    }
    uint32_t h0, h1, l0, l1;
    splitbf(v.x, v.y, h0, l0);
    splitbf(v.z, v.w, h1, l1);
    size_t d = (size_t)r * dstStride + j;
    *reinterpret_cast<uint2*>(hi + d) = make_uint2(h0, h1);
    *reinterpret_cast<uint2*>(lo + d) = make_uint2(l0, l1);
}

// ---------------- prep kernels ----------------
__global__ void transpose_win(const float* __restrict__ W_in)
{
    __shared__ float tile[32][33];
    int j0 = blockIdx.x << 5, h0 = blockIdx.y << 5;
    int tx = threadIdx.x, ty = threadIdx.y;
#pragma unroll
    for (int i = 0; i < 4; i++) {
        int h = h0 + ty + i * 8, j = j0 + tx;
        tile[ty + i * 8][tx] = (j < SDIM + ADIM) ? W_in[(size_t)h * (SDIM + ADIM) + j] : 0.f;
    }
    __syncthreads();
#pragma unroll
    for (int i = 0; i < 4; i++) {
        int j = j0 + ty + i * 8, h = h0 + tx;
        g_wt[(size_t)j * 1024 + h] = tile[tx][ty + i * 8];
    }
}

__global__ void bcomb_kernel(const float* __restrict__ W_ih,
                             const float* __restrict__ b_in,
                             const float* __restrict__ b_ih)
{
    int n = blockIdx.x * (blockDim.x >> 5) + (threadIdx.x >> 5);
    if (n >= 3072) return;
    int lane = threadIdx.x & 31;
    float s = 0.f;
    const float* row = W_ih + (size_t)n * 1024;
    for (int h = lane; h < 1024; h += 32) s += row[h] * b_in[h];
#pragma unroll
    for (int o = 16; o; o >>= 1) s += __shfl_xor_sync(0xFFFFFFFFu, s, o);
    if (lane == 0) g_bc[n] = s + b_ih[n];
}

// ---------------- bf16 hi/lo GEMM, K-chunk 64, 2-stage, dual operand sets ----
#define MMA_THR 512
#define HALF_BYTES 49152
#define STG_BYTES  (2 * HALF_BYTES)
#define SMEM_CA    (2 * STG_BYTES)
#define OFFB_AH 0
#define OFFB_AL 8192
#define OFFB_BH 16384
#define OFFB_BL 32768

struct GemmArgs {
    const __nv_bfloat16 *Ah, *Al, *Bh, *Bl;
    const float* bias;
    float* C;
    int Ntot, K;
};

__device__ __forceinline__ void mma16(float c[4], const uint32_t a[4], const uint32_t b[2]) {
    asm volatile("mma.sync.aligned.m16n8k16.row.col.f32.bf16.bf16.f32 "
                 "{%0,%1,%2,%3}, {%4,%5,%6,%7}, {%8,%9}, {%0,%1,%2,%3};"
                 : "+f"(c[0]), "+f"(c[1]), "+f"(c[2]), "+f"(c[3])
                 : "r"(a[0]), "r"(a[1]), "r"(a[2]), "r"(a[3]), "r"(b[0]), "r"(b[1]));
}
__device__ __forceinline__ void cp16(uint32_t dst, const void* src) {
    asm volatile("cp.async.cg.shared.global [%0], [%1], 16;"
                 :: "r"(dst), "l"(src) : "memory");
}
#define CP_COMMIT() asm volatile("cp.async.commit_group;" ::: "memory")
#define CP_WAIT0()  asm volatile("cp.async.wait_group 0;" ::: "memory")

__global__ __launch_bounds__(MMA_THR, 1)
void bfgemm(GemmArgs arg0, GemmArgs arg1)
{
    extern __shared__ __align__(16) char smc[];
    const uint32_t sbase = smem_u32(smc);
    const uint32_t* smw = reinterpret_cast<const uint32_t*>(smc);

    const GemmArgs& A = blockIdx.z ? arg1 : arg0;
    const __nv_bfloat16* __restrict__ Ah = A.Ah;
    const __nv_bfloat16* __restrict__ Al = A.Al;
    const __nv_bfloat16* __restrict__ Bh = A.Bh;
    const __nv_bfloat16* __restrict__ Bl = A.Bl;
    const int K = A.K;
    const int KC = K >> 6;

    const int bm = blockIdx.y << 7;
    const int bn = blockIdx.x << 8;
    const int t  = threadIdx.x;
    const int wid  = t >> 5;
    const int lane = t & 31;
    const int g = lane >> 2;
    const int c = lane & 3;
    const int wm = (wid >> 2) << 5;
    const int wn = (wid & 3) << 6;

    const int rowA = t >> 2;
    const int qA   = t & 3;
    const uint32_t dA = (uint32_t)(rowA * 64 + ((qA ^ ((rowA >> 1) & 3)) << 4));
    const int rB0 = t >> 2, rB1 = (t + 512) >> 2;
    const uint32_t dB0 = (uint32_t)(rB0 * 64 + ((qA ^ ((rB0 >> 1) & 3)) << 4));
    const uint32_t dB1 = (uint32_t)(rB1 * 64 + ((qA ^ ((rB1 >> 1) & 3)) << 4));

    auto issue_stage = [&](int kc) {
        if (kc < KC) {
            const uint32_t st = sbase + (uint32_t)(kc & 1) * STG_BYTES;
#pragma unroll
            for (int h = 0; h < 2; h++) {
                const uint32_t hb = st + (uint32_t)h * HALF_BYTES;
                const int ke = (kc << 6) + (h << 5) + (qA << 3);
                cp16(hb + OFFB_AH + dA, Ah + (size_t)(bm + rowA) * K + ke);
                cp16(hb + OFFB_AL + dA, Al + (size_t)(bm + rowA) * K + ke);
                cp16(hb + OFFB_BH + dB0, Bh + (size_t)(bn + rB0) * K + ke);
                cp16(hb + OFFB_BH + dB1, Bh + (size_t)(bn + rB1) * K + ke);
                cp16(hb + OFFB_BL + dB0, Bl + (size_t)(bn + rB0) * K + ke);
                cp16(hb + OFFB_BL + dB1, Bl + (size_t)(bn + rB1) * K + ke);
            }
        }
        CP_COMMIT();
    };

    float acc[2][8][4];
#pragma unroll
    for (int i = 0; i < 2; i++)
#pragma unroll
        for (int j = 0; j < 8; j++)
#pragma unroll
            for (int r = 0; r < 4; r++) acc[i][j][r] = 0.f;

    issue_stage(0);

    const int swzf = ((g >> 1) & 3) << 2;

    for (int k = 0; k < KC; k++) {
        CP_WAIT0();
        __syncthreads();
        issue_stage(k + 1);

        const uint32_t stg = (uint32_t)(k & 1) * (STG_BYTES / 4);
#pragma unroll
        for (int h = 0; h < 2; h++) {
            const uint32_t* S  = smw + stg + (uint32_t)h * (HALF_BYTES / 4);
            const uint32_t* AH = S;
            const uint32_t* AL = S + OFFB_AL / 4;
            const uint32_t* BH = S + OFFB_BH / 4;
            const uint32_t* BL = S + OFFB_BL / 4;
#pragma unroll
            for (int ks = 0; ks < 2; ks++) {
                const int w0 = ((ks << 3) + c) ^ swzf;
                const int w1 = ((ks << 3) + 4 + c) ^ swzf;
                uint32_t aH[2][4], aL[2][4];
#pragma unroll
                for (int i = 0; i < 2; i++) {
                    int r0 = (wm + (i << 4) + g) << 4;
                    int r1 = r0 + (8 << 4);
                    aH[i][0] = AH[r0 + w0]; aH[i][1] = AH[r1 + w0];
                    aH[i][2] = AH[r0 + w1]; aH[i][3] = AH[r1 + w1];
                    aL[i][0] = AL[r0 + w0]; aL[i][1] = AL[r1 + w0];
                    aL[i][2] = AL[r0 + w1]; aL[i][3] = AL[r1 + w1];
                }
#pragma unroll
                for (int jp = 0; jp < 4; jp++) {
                    uint32_t bH[2][2], bL[2][2];
#pragma unroll
                    for (int q = 0; q < 2; q++) {
                        int j = jp * 2 + q;
                        int r0 = (wn + (j << 3) + g) << 4;
                        bH[q][0] = BH[r0 + w0]; bH[q][1] = BH[r0 + w1];
                        bL[q][0] = BL[r0 + w0]; bL[q][1] = BL[r0 + w1];
                    }
#pragma unroll
                    for (int i = 0; i < 2; i++)
#pragma unroll
                        for (int q = 0; q < 2; q++) {
                            mma16(acc[i][jp * 2 + q], aH[i], bH[q]);
                            mma16(acc[i][jp * 2 + q], aL[i], bH[q]);
                            mma16(acc[i][jp * 2 + q], aH[i], bL[q]);
                        }
                }
            }
        }
    }

    const float* bias = A.bias;
    float* C = A.C;
    const int Ntot = A.Ntot;
#pragma unroll
    for (int i = 0; i < 2; i++) {
        int row0 = bm + wm + (i << 4) + g;
        int row1 = row0 + 8;
#pragma unroll
        for (int j = 0; j < 8; j++) {
            int col = bn + wn + (j << 3) + (c << 1);
            float2 b2 = *reinterpret_cast<const float2*>(bias + col);
            float2 v0 = make_float2(acc[i][j][0] + b2.x, acc[i][j][1] + b2.y);
            float2 v1 = make_float2(acc[i][j][2] + b2.x, acc[i][j][3] + b2.y);
            *reinterpret_cast<float2*>(C + (size_t)row0 * Ntot + col) = v0;
            *reinterpret_cast<float2*>(C + (size_t)row1 * Ntot + col) = v1;
        }
    }
}

// ---------------- fp32 FFMA GEMM (fix path, 64x64 tile) ----------------
#define GBM 64
#define GBN 64
#define GBK 16
#define GTM 4
#define GTN 4

__global__ __launch_bounds__(256, 4)
void gemm_f32(const float* __restrict__ A1, int K1,
              const float* __restrict__ A2, int K2,
              const float* __restrict__ B,
              const float* __restrict__ bias,
              float* __restrict__ C, int N)
{
    __shared__ __align__(16) float As[GBK][GBM];
    __shared__ __align__(16) float Bs[GBK][GBN];
    const int K  = K1 + K2;
    const int bm = blockIdx.y * GBM;
    const int bn = blockIdx.x * GBN;
    const int t  = threadIdx.x;
    const int tx = t & 15;
    const int ty = t >> 4;

    float acc[GTM][GTN];
#pragma unroll
    for (int i = 0; i < GTM; i++)
#pragma unroll
        for (int j = 0; j < GTN; j++) acc[i][j] = 0.f;

    const int rowL = t >> 2;            // 0..63
    const int kqL  = (t & 3) << 2;

    for (int kt = 0; kt < K; kt += GBK) {
        {
            int kg = kt + kqL;
            int m = bm + rowL;
            float4 v;
            if (kg < K1) v = *reinterpret_cast<const float4*>(A1 + (size_t)m * K1 + kg);
            else         v = *reinterpret_cast<const float4*>(A2 + (size_t)m * K2 + (kg - K1));
            As[kqL + 0][rowL] = v.x; As[kqL + 1][rowL] = v.y;
            As[kqL + 2][rowL] = v.z; As[kqL + 3][rowL] = v.w;
            int n = bn + rowL;
            float4 w = *reinterpret_cast<const float4*>(B + (size_t)n * K + kg);
            Bs[kqL + 0][rowL] = w.x; Bs[kqL + 1][rowL] = w.y;
            Bs[kqL + 2][rowL] = w.z; Bs[kqL + 3][rowL] = w.w;
        }
        __syncthreads();
#pragma unroll
        for (int k = 0; k < GBK; k++) {
            float4 a0 = *reinterpret_cast<const float4*>(&As[k][ty * GTM]);
            float4 b0 = *reinterpret_cast<const float4*>(&Bs[k][tx * GTN]);
            float a[4] = {a0.x, a0.y, a0.z, a0.w};
            float b[4] = {b0.x, b0.y, b0.z, b0.w};
#pragma unroll
            for (int i = 0; i < GTM; i++)
#pragma unroll
                for (int j = 0; j < GTN; j++)
                    acc[i][j] = fmaf(a[i], b[j], acc[i][j]);
        }
        __syncthreads();
    }
#pragma unroll
    for (int i = 0; i < GTM; i++) {
        int m = bm + ty * GTM + i;
        float* crow = C + (size_t)m * N + bn + tx * GTN;
#pragma unroll
        for (int j = 0; j < GTN; j++)
            crow[j] = acc[i][j] + bias[bn + tx * GTN + j];
    }
}

// ---------------- GRU elementwise combine + bf16 h split ----------------
__global__ void gru_kernel(const float* __restrict__ deter,
                           const unsigned char* __restrict__ first,
                           float* __restrict__ h_out)
{
    int e = blockIdx.x * blockDim.x + threadIdx.x;   // pair index
    if (e >= BSZ * REC / 2) return;
    int i0 = e * 2;
    int m = i0 >> 10;
    int n = i0 & 1023;
    float hv[2];
#pragma unroll
    for (int q = 0; q < 2; q++) {
        size_t base = (size_t)m * (3 * REC) + n + q;
        float ir  = g_gi[base];
        float iz  = g_gi[base + REC];
        float i_n = g_gi[base + 2 * REC];
        float hr  = g_gh[base];
        float hz  = g_gh[base + REC];
        float h_n = g_gh[base + 2 * REC];
        float d = first[m] ? 0.f : deter[i0 + q];
        float r  = 1.f / (1.f + expf(-(ir + hr)));
        float z  = 1.f / (1.f + expf(-(iz + hz)));
        float nn = tanhf(i_n + r * h_n);
        hv[q] = (1.f - z) * nn + z * d;
    }
    *reinterpret_cast<float2*>(h_out + i0) = make_float2(hv[0], hv[1]);
    uint32_t hh, ll;
    splitbf(hv[0], hv[1], hh, ll);
    size_t d = (size_t)m * 2048 + n;
    *reinterpret_cast<uint32_t*>(g_ho_h + d) = hh;
    *reinterpret_cast<uint32_t*>(g_ho_l + d) = ll;
}

// ---------------- threefry2x32 + gumbel ----------------
__device__ __forceinline__ uint32_t threefry_bits(uint32_t x1in)
{
    const uint32_t ks0 = 0u;
    const uint32_t ks1 = 42u;
    const uint32_t ks2 = 0x1BD11BDAu ^ ks0 ^ ks1;
    uint32_t x0 = 0u + ks0;
    uint32_t x1 = x1in + ks1;
#define TF_R(r) { x0 += x1; x1 = __funnelshift_l(x1, x1, (r)); x1 ^= x0; }
    TF_R(13) TF_R(15) TF_R(26) TF_R(6)
    x0 += ks1; x1 += ks2 + 1u;
    TF_R(17) TF_R(29) TF_R(16) TF_R(24)
    x0 += ks2; x1 += ks0 + 2u;
    TF_R(13) TF_R(15) TF_R(26) TF_R(6)
    x0 += ks0; x1 += ks1 + 3u;
    TF_R(17) TF_R(29) TF_R(16) TF_R(24)
    x0 += ks1; x1 += ks2 + 4u;
    TF_R(13) TF_R(15) TF_R(26) TF_R(6)
    x0 += ks2; x1 += ks0 + 5u;
#undef TF_R
    return x0 ^ x1;
}

__device__ __forceinline__ float gumbel_at(uint32_t idx)
{
    uint32_t bits = threefry_bits(idx);
    float f = __uint_as_float((bits >> 9) | 0x3f800000u) - 1.0f;
    float u = fmaxf(f, 1.17549435e-38f);
    float inner = -logf(u);
    return -__logf(inner);
}

__global__ void sample_kernel(const float* __restrict__ logits,
                              float* __restrict__ stoch_out)
{
    int g = blockIdx.x * blockDim.x + threadIdx.x;
    if (g >= BSZ * 32) return;
    const float4* lrow = reinterpret_cast<const float4*>(logits + (size_t)g * 32);
    float best = -3.4e38f, second = -3.4e38f;
    int   bi   = 0;
    uint32_t base = (uint32_t)g * 32u;
#pragma unroll
    for (int q = 0; q < 8; q++) {
        float4 lv = lrow[q];
        float l4[4] = {lv.x, lv.y, lv.z, lv.w};
#pragma unroll
        for (int ci = 0; ci < 4; ci++) {
            int d = q * 4 + ci;
            float s = l4[ci] + gumbel_at(base + (uint32_t)d);
            if (s > best) { second = best; best = s; bi = d; }
            else if (s > second) second = s;
        }
    }
    float4* dst = reinterpret_cast<float4*>(stoch_out + (size_t)g * 32);
#pragma unroll
    for (int q = 0; q < 8; q++) {
        float4 v;
        v.x = (bi == q * 4 + 0) ? 1.f : 0.f;
        v.y = (bi == q * 4 + 1) ? 1.f : 0.f;
        v.z = (bi == q * 4 + 2) ? 1.f : 0.f;
        v.w = (bi == q * 4 + 3) ? 1.f : 0.f;
        dst[q] = v;
    }
    if (best - second < FIX_TAU) {
        int slot = atomicAdd(&g_namb, 1);
        if (slot < AMB_CAP) g_amb[slot] = g;
    }
}

// ---------------- fix path ----------------
__global__ void init_fix()
{
    int t = blockIdx.x * blockDim.x + threadIdx.x;
    if (t == 0) { g_namb = 0; g_nrows = 0; }
    for (int i = t; i < BSZ; i += gridDim.x * blockDim.x) g_rowflag[i] = 0;
}

__global__ void gather_rows(const float* __restrict__ stoch,
                            const float* __restrict__ deter,
                            const float* __restrict__ action,
                            const float* __restrict__ obs,
                            const unsigned char* __restrict__ first)
{
    __shared__ int s_row, s_slot;
    int namb = min(g_namb, AMB_CAP);
    for (int e = blockIdx.x; e < namb; e += gridDim.x) {
        if (threadIdx.x == 0) {
            int row = g_amb[e] >> 5;
            int slot = -1;
            if (atomicExch(&g_rowflag[row], 1) == 0) {
                int s = atomicAdd(&g_nrows, 1);
                if (s < FIX_ROWS) { g_rowlist[s] = row; slot = s; }
            }
            s_row = row; s_slot = slot;
        }
        __syncthreads();
        int slot = s_slot, row = s_row;
        if (slot >= 0) {
            bool f = first[row] != 0;
            for (int j = threadIdx.x; j < SDIM; j += blockDim.x)
                g_fin[(size_t)slot * 1088 + j] = f ? 0.f : stoch[(size_t)row * SDIM + j];
            for (int j = threadIdx.x; j < ADIM; j += blockDim.x)
                g_fin[(size_t)slot * 1088 + SDIM + j] = action[(size_t)row * ADIM + j];
            for (int j = threadIdx.x; j < REC; j += blockDim.x)
                g_fdet[(size_t)slot * 1024 + j] = f ? 0.f : deter[(size_t)row * REC + j];
            for (int j = threadIdx.x; j < HID; j += blockDim.x)
                g_fobs[(size_t)slot * 1024 + j] = obs[(size_t)row * HID + j];
        }
        __syncthreads();
    }
}

__global__ void fgru_kernel()
{
    int i = blockIdx.x * blockDim.x + threadIdx.x;
    if (i >= FIX_ROWS * 1024) return;
    int r = i >> 10, n = i & 1023;
    size_t base = (size_t)r * 3072 + n;
    float ir  = g_fgi[base];
    float iz  = g_fgi[base + 1024];
    float i_n = g_fgi[base + 2048];
    float hr  = g_fgh[base];
    float hz  = g_fgh[base + 1024];
    float h_n = g_fgh[base + 2048];
    float d = g_fdet[i];
    float rr = 1.f / (1.f + expf(-(ir + hr)));
    float zz = 1.f / (1.f + expf(-(iz + hz)));
    float nn = tanhf(i_n + rr * h_n);
    g_fh[i] = (1.f - zz) * nn + zz * d;
}

__global__ void fix_sample(float* __restrict__ stoch_out)
{
    int idx = blockIdx.x * blockDim.x + threadIdx.x;
    int r = idx >> 5, gl = idx & 31;
    if (r >= min(g_nrows, FIX_ROWS)) return;
    int row = g_rowlist[r];
    const float* l = g_flog + (size_t)r * 1024 + gl * 32;
    uint32_t base = ((uint32_t)row * 32u + (uint32_t)gl) * 32u;
    float best = -3.4e38f;
    int bi = 0;
#pragma unroll
    for (int d = 0; d < 32; d++) {
        float s = l[d] + gumbel_at(base + (uint32_t)d);
        if (s > best) { best = s; bi = d; }
    }
    float* dst = stoch_out + (size_t)row * 1024 + gl * 32;
#pragma unroll
    for (int d = 0; d < 32; d++) dst[d] = (d == bi) ? 1.f : 0.f;
}

// ---------------- launch ----------------
extern "C" void kernel_launch(void* const* d_in, const int* in_sizes, int n_in,
                              void* d_out, int out_size)
{
    (void)in_sizes; (void)n_in; (void)out_size;
    const float* stoch  = (const float*)d_in[0];
    const float* deter  = (const float*)d_in[1];
    const float* action = (const float*)d_in[3];
    const float* obs    = (const float*)d_in[4];
    const unsigned char* first = (const unsigned char*)d_in[5];
    const float* W_in   = (const float*)d_in[6];
    const float* b_in   = (const float*)d_in[7];
    const float* W_ih   = (const float*)d_in[8];
    const float* b_ih   = (const float*)d_in[9];
    const float* W_hh   = (const float*)d_in[10];
    const float* b_hh   = (const float*)d_in[11];
    const float* W_post = (const float*)d_in[14];
    const float* b_post = (const float*)d_in[15];

    float* out        = (float*)d_out;
    float* h_out      = out;
    float* stoch_out  = out + (size_t)BSZ * LATD;
    float* logits_out = out + 2 * (size_t)BSZ * LATD;

    float *gip, *ghp, *wt, *wc, *bc, *zb;
    float *fin, *fdet, *fobs, *fx, *fgi, *fgh, *fh, *flog;
    __nv_bfloat16 *acth, *actl, *deth, *detl, *hoh, *hol;
    __nv_bfloat16 *wihh, *wihl, *wth, *wtl, *wch, *wcl, *whhh, *whhl, *wph, *wpl;
    cudaGetSymbolAddress((void**)&gip, g_gi);
    cudaGetSymbolAddress((void**)&ghp, g_gh);
    cudaGetSymbolAddress((void**)&wt,  g_wt);
    cudaGetSymbolAddress((void**)&wc,  g_wc);
    cudaGetSymbolAddress((void**)&bc,  g_bc);
    cudaGetSymbolAddress((void**)&zb,  g_zb);
    cudaGetSymbolAddress((void**)&acth, g_act_h); cudaGetSymbolAddress((void**)&actl, g_act_l);
    cudaGetSymbolAddress((void**)&deth, g_det_h); cudaGetSymbolAddress((void**)&detl, g_det_l);
    cudaGetSymbolAddress((void**)&hoh,  g_ho_h);  cudaGetSymbolAddress((void**)&hol,  g_ho_l);
    cudaGetSymbolAddress((void**)&wihh, g_wih_h); cudaGetSymbolAddress((void**)&wihl, g_wih_l);
    cudaGetSymbolAddress((void**)&wth,  g_wt_h);  cudaGetSymbolAddress((void**)&wtl,  g_wt_l);
    cudaGetSymbolAddress((void**)&wch,  g_wc_h);  cudaGetSymbolAddress((void**)&wcl,  g_wc_l);
    cudaGetSymbolAddress((void**)&whhh, g_whh_h); cudaGetSymbolAddress((void**)&whhl, g_whh_l);
    cudaGetSymbolAddress((void**)&wph,  g_wp_h);  cudaGetSymbolAddress((void**)&wpl,  g_wp_l);
    cudaGetSymbolAddress((void**)&fin,  g_fin);
    cudaGetSymbolAddress((void**)&fdet, g_fdet);
    cudaGetSymbolAddress((void**)&fobs, g_fobs);
    cudaGetSymbolAddress((void**)&fx,   g_fx);
    cudaGetSymbolAddress((void**)&fgi,  g_fgi);
    cudaGetSymbolAddress((void**)&fgh,  g_fgh);
    cudaGetSymbolAddress((void**)&fh,   g_fh);
    cudaGetSymbolAddress((void**)&flog, g_flog);

    cudaFuncSetAttribute(bfgemm, cudaFuncAttributeMaxDynamicSharedMemorySize, SMEM_CA);

    dim3 thr(MMA_THR);
    auto blks = [](size_t n) { return (unsigned)((n + 255) / 256); };

    init_fix<<<64, 256>>>();

    // ---- prep: W_comb = W_ih @ W_in ----
    transpose_win<<<dim3(1280 / 32, 1024 / 32), dim3(32, 8)>>>(W_in);
    bcomb_kernel<<<3072 / 8, 256>>>(W_ih, b_in, b_ih);
    split_kernel<<<blks((size_t)3072 * 1024 / 4), 256>>>(
        W_ih, 1024, nullptr, 1024, 0, nullptr, wihh, wihl, 3072, 1024);
    split_kernel<<<blks((size_t)1280 * 1024 / 4), 256>>>(
        wt, 1024, nullptr, 1024, 0, nullptr, wth, wtl, 1280, 1024);
    {
        GemmArgs a{wihh, wihl, wth, wtl, zb, wc, 1280, 1024};
        bfgemm<<<dim3(1280 / 256, 3072 / 128, 1), thr, SMEM_CA>>>(a, a);
    }
    split_kernel<<<blks((size_t)3072 * 1088 / 4), 256>>>(
        wc, 1280, nullptr, 1088, 0, nullptr, wch, wcl, 3072, 1088);

    // ---- split activations + remaining weights + obs (into ho upper half) ----
    split_kernel<<<blks((size_t)BSZ * 1088 / 4), 256>>>(
        stoch, 1024, action, 1024, 64, first, acth, actl, BSZ, 1088);
    split_kernel<<<blks((size_t)BSZ * 1024 / 4), 256>>>(
        deter, 1024, nullptr, 1024, 0, first, deth, detl, BSZ, 1024);
    split_kernel<<<blks((size_t)3072 * 1024 / 4), 256>>>(
        W_hh, 1024, nullptr, 1024, 0, nullptr, whhh, whhl, 3072, 1024);
    split_kernel<<<blks((size_t)1024 * 2048 / 4), 256>>>(
        W_post, 2048, nullptr, 2048, 0, nullptr, wph, wpl, 1024, 2048);
    split_kernel<<<blks((size_t)BSZ * 1024 / 4), 256>>>(
        obs, 1024, nullptr, 1024, 0, nullptr, hoh + 1024, hol + 1024, BSZ, 2048);

    // ---- main GEMMs ----
    {
        GemmArgs agi{acth, actl, wch, wcl, bc, gip, 3072, 1088};
        GemmArgs agh{deth, detl, whhh, whhl, b_hh, ghp, 3072, 1024};
        bfgemm<<<dim3(3072 / 256, BSZ / 128, 2), thr, SMEM_CA>>>(agi, agh);
    }
    gru_kernel<<<(BSZ * REC / 2) / 256, 256>>>(deter, first, h_out);
    {
        GemmArgs alg{hoh, hol, wph, wpl, b_post, logits_out, 1024, 2048};
        bfgemm<<<dim3(1024 / 256, BSZ / 128, 1), thr, SMEM_CA>>>(alg, alg);
    }
    sample_kernel<<<(BSZ * 32) / 256, 256>>>(logits_out, stoch_out);

    // ---- fp32 fix path (exact weights, 64x64 tiles) ----
    gather_rows<<<256, 256>>>(stoch, deter, action, obs, first);
    gemm_f32<<<dim3(HID / GBN, FIX_ROWS / GBM), dim3(256)>>>(
        fin, 1088, fin, 0, W_in, b_in, fx, HID);
    gemm_f32<<<dim3(3 * REC / GBN, FIX_ROWS / GBM), dim3(256)>>>(
        fx, 1024, fx, 0, W_ih, b_ih, fgi, 3 * REC);
    gemm_f32<<<dim3(3 * REC / GBN, FIX_ROWS / GBM), dim3(256)>>>(
        fdet, 1024, fdet, 0, W_hh, b_hh, fgh, 3 * REC);
    fgru_kernel<<<(FIX_ROWS * 1024) / 256, 256>>>();
    gemm_f32<<<dim3(LATD / GBN, FIX_ROWS / GBM), dim3(256)>>>(
        fh, 1024, fobs, 1024, W_post, b_post, flog, LATD);
    fix_sample<<<(FIX_ROWS * 32) / 256, 256>>>(stoch_out);
}